// round 3
// baseline (speedup 1.0000x reference)
#include <cuda_runtime.h>
#include <math.h>

#define BATCH 8
#define CHN 192
#define CH3 576
#define IMH 128
#define IMW 128
#define NPIX (IMH*IMW)         // 16384
#define NHEADS 4
#define HDIM 48
#define NORI 9
#define NSPLIT 32
#define SPLITLEN (NPIX/NSPLIT) // 512
#define PI_F 3.14159265358979323846f

// ---- device scratch (no allocation allowed) ----
__device__ float g_qkv  [BATCH*CH3*NPIX];
__device__ float g_qkvdw[BATCH*CH3*NPIX];
__device__ float g_hogw [BATCH*NORI*NPIX];
__device__ float g_normp[2*BATCH*CHN*16];   // per-rowblock partial sum-squares
__device__ float g_norms[2*BATCH*CHN];
__device__ float g_attnp[BATCH*NHEADS*NSPLIT*HDIM*HDIM];
__device__ float g_attn [BATCH*NHEADS*HDIM*HDIM];
__device__ float g_wf   [BATCH*CHN*CHN];

__device__ __forceinline__ unsigned f2tf32(float x) {
    unsigned r;
    asm("cvt.rna.tf32.f32 %0, %1;" : "=r"(r) : "f"(x));
    return r;
}

// ============================================================
// tf32 tensor-core GEMM: C[z] (MxN) = A[z](MxK, lda=K) * B[z](KxN, ldb=N)
// BM=128 BN=128 BK=16, 256 thr (8 warps 2x4), warp tile 64x32 (mt=4,nt=4)
// mma.sync.m16n8k8 tf32, double-buffered smem (pad 136 -> conflict-free),
// M masked (clamped loads, predicated stores). N%128==0, K%16==0.
// ============================================================
__global__ __launch_bounds__(256, 1)
void gemm_tf32_kernel(const float* __restrict__ A, long sA,
                      const float* __restrict__ B, long sB,
                      float* __restrict__ Cm, long sC,
                      int M, int N, int K)
{
    __shared__ unsigned As[2][16][136];   // [k][m], pad 8 mod 32
    __shared__ unsigned Bs[2][16][136];   // [k][n]

    const int t = threadIdx.x;
    const int lane = t & 31;
    const int warp = t >> 5;
    const int wm = warp >> 2;        // 0..1
    const int wn = warp & 3;         // 0..3
    const int m0 = blockIdx.y * 128;
    const int n0 = blockIdx.x * 128;
    const float* Ab = A + (long)blockIdx.z * sA;
    const float* Bb = B + (long)blockIdx.z * sB;
    float*       Cb = Cm + (long)blockIdx.z * sC;

    const int arow = t >> 2;          // 0..63 (handles arow and arow+64)
    const int ac4  = t & 3;           // k-quad
    const int brow = t >> 5;          // 0..7 (handles brow, brow+8)
    const int bc4  = t & 31;

    const int kc = lane & 3;

    float acc[4][4][4];
#pragma unroll
    for (int i = 0; i < 4; i++)
#pragma unroll
        for (int j = 0; j < 4; j++)
#pragma unroll
            for (int r = 0; r < 4; r++) acc[i][j][r] = 0.f;

    const int niter = K / 16;

    // ---- preload iter 0 into buf 0 ----
    {
        int r0 = min(m0 + arow, M - 1);
        int r1 = min(m0 + arow + 64, M - 1);
        float4 va0 = *(const float4*)(Ab + (long)r0 * K + ac4 * 4);
        float4 va1 = *(const float4*)(Ab + (long)r1 * K + ac4 * 4);
        As[0][ac4*4+0][arow] = f2tf32(va0.x); As[0][ac4*4+1][arow] = f2tf32(va0.y);
        As[0][ac4*4+2][arow] = f2tf32(va0.z); As[0][ac4*4+3][arow] = f2tf32(va0.w);
        As[0][ac4*4+0][arow+64] = f2tf32(va1.x); As[0][ac4*4+1][arow+64] = f2tf32(va1.y);
        As[0][ac4*4+2][arow+64] = f2tf32(va1.z); As[0][ac4*4+3][arow+64] = f2tf32(va1.w);
        float4 vb0 = *(const float4*)(Bb + (long)brow * N + n0 + bc4 * 4);
        float4 vb1 = *(const float4*)(Bb + (long)(brow + 8) * N + n0 + bc4 * 4);
        Bs[0][brow][bc4*4+0] = f2tf32(vb0.x); Bs[0][brow][bc4*4+1] = f2tf32(vb0.y);
        Bs[0][brow][bc4*4+2] = f2tf32(vb0.z); Bs[0][brow][bc4*4+3] = f2tf32(vb0.w);
        Bs[0][brow+8][bc4*4+0] = f2tf32(vb1.x); Bs[0][brow+8][bc4*4+1] = f2tf32(vb1.y);
        Bs[0][brow+8][bc4*4+2] = f2tf32(vb1.z); Bs[0][brow+8][bc4*4+3] = f2tf32(vb1.w);
    }
    __syncthreads();

    int cur = 0;
    for (int it = 0; it < niter; it++) {
        float4 va0_n, va1_n, vb0_n, vb1_n;
        const bool more = (it + 1) < niter;
        if (more) {
            int k0 = (it + 1) * 16;
            int r0 = min(m0 + arow, M - 1);
            int r1 = min(m0 + arow + 64, M - 1);
            va0_n = *(const float4*)(Ab + (long)r0 * K + k0 + ac4 * 4);
            va1_n = *(const float4*)(Ab + (long)r1 * K + k0 + ac4 * 4);
            vb0_n = *(const float4*)(Bb + (long)(k0 + brow) * N + n0 + bc4 * 4);
            vb1_n = *(const float4*)(Bb + (long)(k0 + brow + 8) * N + n0 + bc4 * 4);
        }

#pragma unroll
        for (int kk = 0; kk < 2; kk++) {
            const int kb = kk * 8;
            unsigned af[4][4], bf[4][2];
#pragma unroll
            for (int mt = 0; mt < 4; mt++) {
                int r = wm * 64 + mt * 16 + (lane >> 2);
                af[mt][0] = As[cur][kb + kc    ][r];
                af[mt][1] = As[cur][kb + kc    ][r + 8];
                af[mt][2] = As[cur][kb + kc + 4][r];
                af[mt][3] = As[cur][kb + kc + 4][r + 8];
            }
#pragma unroll
            for (int nt = 0; nt < 4; nt++) {
                int c = wn * 32 + nt * 8 + (lane >> 2);
                bf[nt][0] = Bs[cur][kb + kc    ][c];
                bf[nt][1] = Bs[cur][kb + kc + 4][c];
            }
#pragma unroll
            for (int mt = 0; mt < 4; mt++)
#pragma unroll
                for (int nt = 0; nt < 4; nt++) {
                    asm volatile(
                        "mma.sync.aligned.m16n8k8.row.col.f32.tf32.tf32.f32 "
                        "{%0,%1,%2,%3}, {%4,%5,%6,%7}, {%8,%9}, {%0,%1,%2,%3};\n"
                        : "+f"(acc[mt][nt][0]), "+f"(acc[mt][nt][1]),
                          "+f"(acc[mt][nt][2]), "+f"(acc[mt][nt][3])
                        : "r"(af[mt][0]), "r"(af[mt][1]), "r"(af[mt][2]), "r"(af[mt][3]),
                          "r"(bf[nt][0]), "r"(bf[nt][1]));
                }
        }

        if (more) {
            int nxt = cur ^ 1;
            As[nxt][ac4*4+0][arow] = f2tf32(va0_n.x); As[nxt][ac4*4+1][arow] = f2tf32(va0_n.y);
            As[nxt][ac4*4+2][arow] = f2tf32(va0_n.z); As[nxt][ac4*4+3][arow] = f2tf32(va0_n.w);
            As[nxt][ac4*4+0][arow+64] = f2tf32(va1_n.x); As[nxt][ac4*4+1][arow+64] = f2tf32(va1_n.y);
            As[nxt][ac4*4+2][arow+64] = f2tf32(va1_n.z); As[nxt][ac4*4+3][arow+64] = f2tf32(va1_n.w);
            Bs[nxt][brow][bc4*4+0] = f2tf32(vb0_n.x); Bs[nxt][brow][bc4*4+1] = f2tf32(vb0_n.y);
            Bs[nxt][brow][bc4*4+2] = f2tf32(vb0_n.z); Bs[nxt][brow][bc4*4+3] = f2tf32(vb0_n.w);
            Bs[nxt][brow+8][bc4*4+0] = f2tf32(vb1_n.x); Bs[nxt][brow+8][bc4*4+1] = f2tf32(vb1_n.y);
            Bs[nxt][brow+8][bc4*4+2] = f2tf32(vb1_n.z); Bs[nxt][brow+8][bc4*4+3] = f2tf32(vb1_n.w);
            __syncthreads();
            cur = nxt;
        }
    }

    // epilogue (M-masked)
#pragma unroll
    for (int mt = 0; mt < 4; mt++) {
        int r = m0 + wm * 64 + mt * 16 + (lane >> 2);
#pragma unroll
        for (int nt = 0; nt < 4; nt++) {
            int c = n0 + wn * 32 + nt * 8 + (lane & 3) * 2;
            if (r < M)
                *(float2*)(Cb + (long)r * N + c) =
                    make_float2(acc[mt][nt][0], acc[mt][nt][1]);
            if (r + 8 < M)
                *(float2*)(Cb + (long)(r + 8) * N + c) =
                    make_float2(acc[mt][nt][2], acc[mt][nt][3]);
        }
    }
}

// ============================================================
// Sobel (replicate pad, /8 kernels) -> channel-mean mag/ang -> HOG weights
// ============================================================
__global__ __launch_bounds__(128)
void sobel_hog_kernel(const float* __restrict__ x)
{
    const int w = threadIdx.x;
    const int h = blockIdx.x;
    const int b = blockIdx.y;
    const int hm = h > 0 ? h - 1 : 0;
    const int hp = h < IMH - 1 ? h + 1 : IMH - 1;
    const int wm = w > 0 ? w - 1 : 0;
    const int wp = w < IMW - 1 ? w + 1 : IMW - 1;
    const float* xb = x + (long)b * CHN * NPIX;

    float msum = 0.f, asum = 0.f;
    for (int c = 0; c < CHN; c++) {
        const float* p = xb + (long)c * NPIX;
        float a00 = __ldg(p + hm*IMW + wm), a01 = __ldg(p + hm*IMW + w), a02 = __ldg(p + hm*IMW + wp);
        float a10 = __ldg(p + h *IMW + wm),                              a12 = __ldg(p + h *IMW + wp);
        float a20 = __ldg(p + hp*IMW + wm), a21 = __ldg(p + hp*IMW + w), a22 = __ldg(p + hp*IMW + wp);
        float dx = (a02 - a00 + 2.f*(a12 - a10) + a22 - a20) * 0.125f;
        float dy = (a20 - a00 + 2.f*(a21 - a01) + a22 - a02) * 0.125f;
        msum += sqrtf(dx*dx + dy*dy + 1e-6f);
        asum += atan2f(dy, dx + 1e-6f);
    }
    float mag = msum * (1.f / CHN);
    float ang = asum * (1.f / CHN);
    ang = ang - PI_F * floorf(ang / PI_F);
    const float binw = PI_F / NORI;
    const int pix = h * IMW + w;
#pragma unroll
    for (int o = 0; o < NORI; o++) {
        float cen = ((float)o + 0.5f) * binw;
        float wgt = 1.f - fabsf(ang - cen) / binw;
        wgt = wgt > 0.f ? wgt : 0.f;
        g_hogw[((long)b * NORI + o) * NPIX + pix] = wgt * mag;
    }
}

// ============================================================
// Depthwise 3x3 SAME (zero pad), 4 px/thread, fused HOG add on v channels,
// fused sum-of-squares partials for q/k channels.
// grid (1, IMH/8, BATCH*CH3), block (32,8).
// ============================================================
__global__ __launch_bounds__(256)
void dwconv_hog_kernel(const float* __restrict__ Wdw, const float* __restrict__ Whog)
{
    const int plane = blockIdx.z;
    const int b  = plane / CH3;
    const int ch = plane - b * CH3;
    const int w0 = threadIdx.x * 4;
    const int h  = blockIdx.y * 8 + threadIdx.y;
    const float* in = g_qkv + (long)plane * NPIX;
    const float* kw = Wdw + ch * 9;
    float k0 = __ldg(kw+0), k1 = __ldg(kw+1), k2 = __ldg(kw+2);
    float k3 = __ldg(kw+3), k4 = __ldg(kw+4), k5 = __ldg(kw+5);
    float k6 = __ldg(kw+6), k7 = __ldg(kw+7), k8 = __ldg(kw+8);

    float row[3][6];
#pragma unroll
    for (int rr = 0; rr < 3; rr++) {
        int hh = h + rr - 1;
        if (hh >= 0 && hh < IMH) {
            const float* p = in + hh * IMW + w0;
            float4 cv = *(const float4*)p;
            row[rr][1] = cv.x; row[rr][2] = cv.y; row[rr][3] = cv.z; row[rr][4] = cv.w;
            row[rr][0] = (w0 > 0)       ? __ldg(p - 1) : 0.f;
            row[rr][5] = (w0 + 4 < IMW) ? __ldg(p + 4) : 0.f;
        } else {
#pragma unroll
            for (int j = 0; j < 6; j++) row[rr][j] = 0.f;
        }
    }

    float out[4];
#pragma unroll
    for (int j = 0; j < 4; j++) {
        out[j] = k0*row[0][j] + k1*row[0][j+1] + k2*row[0][j+2]
               + k3*row[1][j] + k4*row[1][j+1] + k5*row[1][j+2]
               + k6*row[2][j] + k7*row[2][j+1] + k8*row[2][j+2];
    }

    const int pix = h * IMW + w0;
    if (ch >= 2 * CHN) {
        int d = ch - 2 * CHN;
        const float* hw = g_hogw + (long)b * NORI * NPIX + pix;
#pragma unroll
        for (int o = 0; o < NORI; o++) {
            float wgt = __ldg(Whog + d * NORI + o);
            float4 hv = *(const float4*)(hw + (long)o * NPIX);
            out[0] += wgt * hv.x; out[1] += wgt * hv.y;
            out[2] += wgt * hv.z; out[3] += wgt * hv.w;
        }
    }
    *(float4*)(g_qkvdw + (long)plane * NPIX + pix) =
        make_float4(out[0], out[1], out[2], out[3]);

    if (ch < 2 * CHN) {   // uniform per block
        float ss = out[0]*out[0] + out[1]*out[1] + out[2]*out[2] + out[3]*out[3];
#pragma unroll
        for (int o = 16; o > 0; o >>= 1) ss += __shfl_down_sync(0xffffffffu, ss, o);
        __shared__ float red[8];
        if (threadIdx.x == 0) red[threadIdx.y] = ss;
        __syncthreads();
        if (threadIdx.y == 0 && threadIdx.x == 0) {
            float s = 0.f;
#pragma unroll
            for (int i = 0; i < 8; i++) s += red[i];
            int which = ch / CHN;
            int r = which * (BATCH * CHN) + b * CHN + (ch - which * CHN);
            g_normp[r * 16 + blockIdx.y] = s;
        }
    }
}

// ============================================================
// reduce 16 partials per row -> sqrt -> g_norms. 3072 entries.
// ============================================================
__global__ __launch_bounds__(256)
void norm_reduce_kernel()
{
    int r = blockIdx.x * 256 + threadIdx.x;
    if (r >= 2 * BATCH * CHN) return;
    float s = 0.f;
#pragma unroll
    for (int i = 0; i < 16; i++) s += g_normp[r * 16 + i];
    g_norms[r] = sqrtf(s);
}

// ============================================================
// attn partial: S[bh,split][c][d] = sum_{n in split} q[c,n]*k[d,n]
// ============================================================
__global__ __launch_bounds__(256)
void attn_partial_kernel()
{
    const int bh = blockIdx.x;
    const int split = blockIdx.y;
    const int b = bh >> 2, hh = bh & 3;
    const float* Q  = g_qkvdw + ((long)b * CH3 + hh * HDIM) * NPIX;
    const float* Kp = g_qkvdw + ((long)b * CH3 + CHN + hh * HDIM) * NPIX;
    __shared__ float Qs[32][HDIM + 1];
    __shared__ float Ks[32][HDIM + 1];
    const int t = threadIdx.x;
    const int ty = t >> 4, tx = t & 15;
    float acc[3][3];
#pragma unroll
    for (int i = 0; i < 3; i++)
#pragma unroll
        for (int j = 0; j < 3; j++) acc[i][j] = 0.f;

    const int nbase = split * SPLITLEN;
    for (int chunk = 0; chunk < SPLITLEN; chunk += 32) {
#pragma unroll
        for (int i = 0; i < 6; i++) {
            int e = t + i * 256;
            int c = e >> 5, kk = e & 31;
            Qs[kk][c] = Q [(long)c * NPIX + nbase + chunk + kk];
            Ks[kk][c] = Kp[(long)c * NPIX + nbase + chunk + kk];
        }
        __syncthreads();
#pragma unroll
        for (int kk = 0; kk < 32; kk++) {
            float q0 = Qs[kk][ty*3+0], q1 = Qs[kk][ty*3+1], q2 = Qs[kk][ty*3+2];
            float c0 = Ks[kk][tx*3+0], c1 = Ks[kk][tx*3+1], c2 = Ks[kk][tx*3+2];
            acc[0][0] += q0*c0; acc[0][1] += q0*c1; acc[0][2] += q0*c2;
            acc[1][0] += q1*c0; acc[1][1] += q1*c1; acc[1][2] += q1*c2;
            acc[2][0] += q2*c0; acc[2][1] += q2*c1; acc[2][2] += q2*c2;
        }
        __syncthreads();
    }
    float* dst = g_attnp + ((long)bh * NSPLIT + split) * HDIM * HDIM;
#pragma unroll
    for (int i = 0; i < 3; i++)
#pragma unroll
        for (int j = 0; j < 3; j++)
            dst[(ty*3 + i) * HDIM + tx*3 + j] = acc[i][j];
}

// ============================================================
// reduce splits + normalize + softmax
// ============================================================
__global__ __launch_bounds__(64)
void softmax_kernel(const float* __restrict__ temp)
{
    const int blk = blockIdx.x;
    const int c  = blk % HDIM;
    const int bh = blk / HDIM;
    const int b = bh >> 2, hh = bh & 3;
    const int d = threadIdx.x;
    __shared__ float red[64];
    float val = -1e30f;
    if (d < HDIM) {
        const float* p = g_attnp + (long)bh * NSPLIT * HDIM * HDIM + c * HDIM + d;
        float s = 0.f;
#pragma unroll
        for (int sp = 0; sp < NSPLIT; sp++) s += p[(long)sp * HDIM * HDIM];
        float nq = g_norms[b * CHN + hh * HDIM + c];
        float nk = g_norms[BATCH * CHN + b * CHN + hh * HDIM + d];
        val = s / (fmaxf(nq, 1e-12f) * fmaxf(nk, 1e-12f)) * __ldg(temp + hh);
    }
    red[d] = val; __syncthreads();
    for (int o = 32; o > 0; o >>= 1) { if (d < o) red[d] = fmaxf(red[d], red[d + o]); __syncthreads(); }
    float mx = red[0]; __syncthreads();
    float e = (d < HDIM) ? expf(val - mx) : 0.f;
    red[d] = e; __syncthreads();
    for (int o = 32; o > 0; o >>= 1) { if (d < o) red[d] += red[d + o]; __syncthreads(); }
    if (d < HDIM)
        g_attn[(long)bh * HDIM * HDIM + c * HDIM + d] = e / red[0];
}

// ============================================================
// Fold W_proj with block-diagonal attn
// ============================================================
__global__ __launch_bounds__(256)
void wf_kernel(const float* __restrict__ Wproj)
{
    const int b = blockIdx.x, hh = blockIdx.y;
    __shared__ float at[HDIM][HDIM];
    const int t = threadIdx.x;
    for (int i = t; i < HDIM * HDIM; i += 256)
        at[i / HDIM][i % HDIM] = g_attn[(long)(b * NHEADS + hh) * HDIM * HDIM + i];
    __syncthreads();
    for (int i = t; i < CHN * HDIM; i += 256) {
        int e = i / HDIM, d = i - e * HDIM;
        const float* wp = Wproj + (long)e * CHN + hh * HDIM;
        float acc = 0.f;
#pragma unroll
        for (int c2 = 0; c2 < HDIM; c2++) acc += __ldg(wp + c2) * at[c2][d];
        g_wf[((long)b * CHN + e) * CHN + hh * HDIM + d] = acc;
    }
}

// ============================================================
extern "C" void kernel_launch(void* const* d_in, const int* in_sizes, int n_in,
                              void* d_out, int out_size)
{
    const float* x     = (const float*)d_in[0];
    const float* Wqkv  = (const float*)d_in[1];
    const float* Wdw   = (const float*)d_in[2];
    const float* Whog  = (const float*)d_in[3];
    const float* Wproj = (const float*)d_in[4];
    const float* temp  = (const float*)d_in[5];
    float* out = (float*)d_out;

    void *p_qkv, *p_qkvdw, *p_wf;
    cudaGetSymbolAddress(&p_qkv,   g_qkv);
    cudaGetSymbolAddress(&p_qkvdw, g_qkvdw);
    cudaGetSymbolAddress(&p_wf,    g_wf);

    // 1) qkv = W_qkv @ x     (M=576, K=192, N=16384 per batch) — tf32 MMA
    gemm_tf32_kernel<<<dim3(NPIX / 128, (CH3 + 127) / 128, BATCH), 256>>>(
        Wqkv, 0L,
        x, (long)CHN * NPIX,
        (float*)p_qkv, (long)CH3 * NPIX,
        CH3, NPIX, CHN);

    // 2) Sobel + HOG bin weights
    sobel_hog_kernel<<<dim3(IMH, BATCH), 128>>>(x);

    // 3) depthwise 3x3 (+hog add on v, +norm partials on q/k)
    dwconv_hog_kernel<<<dim3(1, IMH / 8, BATCH * CH3), dim3(32, 8)>>>(Wdw, Whog);

    // 4) reduce norm partials
    norm_reduce_kernel<<<(2 * BATCH * CHN + 255) / 256, 256>>>();

    // 5) q.k^T partial dots (split-K)
    attn_partial_kernel<<<dim3(BATCH * NHEADS, NSPLIT), 256>>>();

    // 6) reduce + scale + softmax
    softmax_kernel<<<BATCH * NHEADS * HDIM, 64>>>(temp);

    // 7) fold W_proj with attn -> per-batch 192x192
    wf_kernel<<<dim3(BATCH, NHEADS), 256>>>(Wproj);

    // 8) out = Wf @ v         (M=192, K=192, N=16384 per batch) — tf32 MMA
    gemm_tf32_kernel<<<dim3(NPIX / 128, (CHN + 127) / 128, BATCH), 256>>>(
        (const float*)p_wf, (long)CHN * CHN,
        (const float*)p_qkvdw + (long)2 * CHN * NPIX, (long)CH3 * NPIX,
        out, (long)CHN * NPIX,
        CHN, NPIX, CHN);
}

// round 4
// speedup vs baseline: 1.2021x; 1.2021x over previous
#include <cuda_runtime.h>
#include <math.h>
#include <stdint.h>

#define BATCH 8
#define CHN 192
#define CH3 576
#define IMH 128
#define IMW 128
#define NPIX (IMH*IMW)         // 16384
#define NHEADS 4
#define HDIM 48
#define NORI 9
#define NSPLIT 32
#define SPLITLEN (NPIX/NSPLIT) // 512
#define PI_F 3.14159265358979323846f
#define GS 3                   // cp.async pipeline stages

// ---- device scratch (no allocation allowed) ----
__device__ float g_qkv  [BATCH*CH3*NPIX];
__device__ float g_qkvdw[BATCH*CH3*NPIX];
__device__ float g_hogw [BATCH*NORI*NPIX];
__device__ float g_normp[2*BATCH*CHN*16];
__device__ float g_norms[2*BATCH*CHN];
__device__ float g_attnp[BATCH*NHEADS*NSPLIT*HDIM*HDIM];
__device__ float g_attn [BATCH*NHEADS*HDIM*HDIM];
__device__ float g_wf   [BATCH*CHN*CHN];

__device__ __forceinline__ unsigned f2tf32(float x) {
    unsigned r;
    asm("cvt.rna.tf32.f32 %0, %1;" : "=r"(r) : "f"(x));
    return r;
}
__device__ __forceinline__ uint32_t smem_u32(const void* p) {
    return (uint32_t)__cvta_generic_to_shared(p);
}
__device__ __forceinline__ void cp_async16(uint32_t dst, const void* src) {
    asm volatile("cp.async.cg.shared.global [%0], [%1], 16;\n" :: "r"(dst), "l"(src));
}
__device__ __forceinline__ void cp_commit() {
    asm volatile("cp.async.commit_group;\n");
}
__device__ __forceinline__ void cp_wait2() {
    asm volatile("cp.async.wait_group %0;\n" :: "n"(GS - 1));
}

// ============================================================
// tf32 tensor-core GEMM, 3-stage cp.async pipeline.
// C[z] (MxN) = A[z](MxK, lda=K) * B[z](KxN, ldb=N)
// BM=64 BN=128 BK=16, 256 thr (8 warps 2x4), warp tile 32x32.
// Raw fp32 in smem; cvt.rna.tf32 at fragment load (numerics identical
// to converting at store). Requires M%64==0, N%128==0, K%16==0.
// As [m][k] pad 20, Bs [k][n] pad 132 -> conflict-free fragment LDS.
// smem = 3*(5120+8448) = 40.7 KB.
// ============================================================
__global__ __launch_bounds__(256)
void gemm_tf32_kernel(const float* __restrict__ A, long sA,
                      const float* __restrict__ B, long sB,
                      float* __restrict__ Cm, long sC,
                      int N, int K)
{
    __shared__ float As[GS][64 * 20];
    __shared__ float Bs[GS][16 * 132];

    const int t = threadIdx.x;
    const int lane = t & 31;
    const int warp = t >> 5;
    const int wm = warp >> 2;        // 0..1
    const int wn = warp & 3;         // 0..3
    const int m0 = blockIdx.y * 64;
    const int n0 = blockIdx.x * 128;
    const float* Ab = A + (long)blockIdx.z * sA;
    const float* Bb = B + (long)blockIdx.z * sB;
    float*       Cb = Cm + (long)blockIdx.z * sC;

    const int am = t >> 2;           // 0..63  (A row)
    const int ac = t & 3;            // A 16B-chunk within 16 k's
    const int bk1 = t >> 5;          // 0..7   (B row, first half)
    const int bc1 = t & 31;          // B 16B-chunk
    const int kc = lane & 3;
    const int lq = lane >> 2;

    const int niter = K / 16;

    float acc[2][4][4];
#pragma unroll
    for (int i = 0; i < 2; i++)
#pragma unroll
        for (int j = 0; j < 4; j++)
#pragma unroll
            for (int r = 0; r < 4; r++) acc[i][j][r] = 0.f;

    // issue cp.async loads for k-iteration `it` into stage it%GS
    auto issue_stage = [&](int it) {
        const int stg = it % GS;
        const int k0 = it * 16;
        cp_async16(smem_u32(&As[stg][am * 20 + ac * 4]),
                   Ab + (long)(m0 + am) * K + k0 + ac * 4);
        cp_async16(smem_u32(&Bs[stg][bk1 * 132 + bc1 * 4]),
                   Bb + (long)(k0 + bk1) * N + n0 + bc1 * 4);
        cp_async16(smem_u32(&Bs[stg][(bk1 + 8) * 132 + bc1 * 4]),
                   Bb + (long)(k0 + bk1 + 8) * N + n0 + bc1 * 4);
    };

    // prologue: stages 0..GS-2
#pragma unroll
    for (int s = 0; s < GS - 1; s++) {
        if (s < niter) issue_stage(s);
        cp_commit();
    }

    for (int it = 0; it < niter; it++) {
        if (it + GS - 1 < niter) issue_stage(it + GS - 1);
        cp_commit();
        cp_wait2();               // stage `it` complete
        __syncthreads();

        const float* Ast = As[it % GS];
        const float* Bst = Bs[it % GS];

#pragma unroll
        for (int kk = 0; kk < 2; kk++) {
            const int kb = kk * 8;
            unsigned af[2][4], bf[4][2];
#pragma unroll
            for (int mt = 0; mt < 2; mt++) {
                int r = wm * 32 + mt * 16 + lq;
                af[mt][0] = f2tf32(Ast[r * 20 + kb + kc]);
                af[mt][1] = f2tf32(Ast[(r + 8) * 20 + kb + kc]);
                af[mt][2] = f2tf32(Ast[r * 20 + kb + kc + 4]);
                af[mt][3] = f2tf32(Ast[(r + 8) * 20 + kb + kc + 4]);
            }
#pragma unroll
            for (int nt = 0; nt < 4; nt++) {
                int c = wn * 32 + nt * 8 + lq;
                bf[nt][0] = f2tf32(Bst[(kb + kc) * 132 + c]);
                bf[nt][1] = f2tf32(Bst[(kb + kc + 4) * 132 + c]);
            }
#pragma unroll
            for (int mt = 0; mt < 2; mt++)
#pragma unroll
                for (int nt = 0; nt < 4; nt++) {
                    asm volatile(
                        "mma.sync.aligned.m16n8k8.row.col.f32.tf32.tf32.f32 "
                        "{%0,%1,%2,%3}, {%4,%5,%6,%7}, {%8,%9}, {%0,%1,%2,%3};\n"
                        : "+f"(acc[mt][nt][0]), "+f"(acc[mt][nt][1]),
                          "+f"(acc[mt][nt][2]), "+f"(acc[mt][nt][3])
                        : "r"(af[mt][0]), "r"(af[mt][1]), "r"(af[mt][2]), "r"(af[mt][3]),
                          "r"(bf[nt][0]), "r"(bf[nt][1]));
                }
        }
        __syncthreads();          // compute done before stage buffer reused
    }

    // epilogue
#pragma unroll
    for (int mt = 0; mt < 2; mt++) {
        int r = m0 + wm * 32 + mt * 16 + lq;
#pragma unroll
        for (int nt = 0; nt < 4; nt++) {
            int c = n0 + wn * 32 + nt * 8 + kc * 2;
            *(float2*)(Cb + (long)r * N + c) =
                make_float2(acc[mt][nt][0], acc[mt][nt][1]);
            *(float2*)(Cb + (long)(r + 8) * N + c) =
                make_float2(acc[mt][nt][2], acc[mt][nt][3]);
        }
    }
}

// ============================================================
// Sobel (replicate pad, /8 kernels) -> channel-mean mag/ang -> HOG weights
// ============================================================
__global__ __launch_bounds__(128)
void sobel_hog_kernel(const float* __restrict__ x)
{
    const int w = threadIdx.x;
    const int h = blockIdx.x;
    const int b = blockIdx.y;
    const int hm = h > 0 ? h - 1 : 0;
    const int hp = h < IMH - 1 ? h + 1 : IMH - 1;
    const int wm = w > 0 ? w - 1 : 0;
    const int wp = w < IMW - 1 ? w + 1 : IMW - 1;
    const float* xb = x + (long)b * CHN * NPIX;

    float msum = 0.f, asum = 0.f;
    for (int c = 0; c < CHN; c++) {
        const float* p = xb + (long)c * NPIX;
        float a00 = __ldg(p + hm*IMW + wm), a01 = __ldg(p + hm*IMW + w), a02 = __ldg(p + hm*IMW + wp);
        float a10 = __ldg(p + h *IMW + wm),                              a12 = __ldg(p + h *IMW + wp);
        float a20 = __ldg(p + hp*IMW + wm), a21 = __ldg(p + hp*IMW + w), a22 = __ldg(p + hp*IMW + wp);
        float dx = (a02 - a00 + 2.f*(a12 - a10) + a22 - a20) * 0.125f;
        float dy = (a20 - a00 + 2.f*(a21 - a01) + a22 - a02) * 0.125f;
        msum += sqrtf(dx*dx + dy*dy + 1e-6f);
        asum += atan2f(dy, dx + 1e-6f);
    }
    float mag = msum * (1.f / CHN);
    float ang = asum * (1.f / CHN);
    ang = ang - PI_F * floorf(ang / PI_F);
    const float binw = PI_F / NORI;
    const int pix = h * IMW + w;
#pragma unroll
    for (int o = 0; o < NORI; o++) {
        float cen = ((float)o + 0.5f) * binw;
        float wgt = 1.f - fabsf(ang - cen) / binw;
        wgt = wgt > 0.f ? wgt : 0.f;
        g_hogw[((long)b * NORI + o) * NPIX + pix] = wgt * mag;
    }
}

// ============================================================
// Depthwise 3x3 SAME (zero pad), 4 px/thread, fused HOG add on v channels,
// fused sum-of-squares partials for q/k channels.
// grid (1, IMH/8, BATCH*CH3), block (32,8).
// ============================================================
__global__ __launch_bounds__(256)
void dwconv_hog_kernel(const float* __restrict__ Wdw, const float* __restrict__ Whog)
{
    const int plane = blockIdx.z;
    const int b  = plane / CH3;
    const int ch = plane - b * CH3;
    const int w0 = threadIdx.x * 4;
    const int h  = blockIdx.y * 8 + threadIdx.y;
    const float* in = g_qkv + (long)plane * NPIX;
    const float* kw = Wdw + ch * 9;
    float k0 = __ldg(kw+0), k1 = __ldg(kw+1), k2 = __ldg(kw+2);
    float k3 = __ldg(kw+3), k4 = __ldg(kw+4), k5 = __ldg(kw+5);
    float k6 = __ldg(kw+6), k7 = __ldg(kw+7), k8 = __ldg(kw+8);

    float row[3][6];
#pragma unroll
    for (int rr = 0; rr < 3; rr++) {
        int hh = h + rr - 1;
        if (hh >= 0 && hh < IMH) {
            const float* p = in + hh * IMW + w0;
            float4 cv = *(const float4*)p;
            row[rr][1] = cv.x; row[rr][2] = cv.y; row[rr][3] = cv.z; row[rr][4] = cv.w;
            row[rr][0] = (w0 > 0)       ? __ldg(p - 1) : 0.f;
            row[rr][5] = (w0 + 4 < IMW) ? __ldg(p + 4) : 0.f;
        } else {
#pragma unroll
            for (int j = 0; j < 6; j++) row[rr][j] = 0.f;
        }
    }

    float out[4];
#pragma unroll
    for (int j = 0; j < 4; j++) {
        out[j] = k0*row[0][j] + k1*row[0][j+1] + k2*row[0][j+2]
               + k3*row[1][j] + k4*row[1][j+1] + k5*row[1][j+2]
               + k6*row[2][j] + k7*row[2][j+1] + k8*row[2][j+2];
    }

    const int pix = h * IMW + w0;
    if (ch >= 2 * CHN) {
        int d = ch - 2 * CHN;
        const float* hw = g_hogw + (long)b * NORI * NPIX + pix;
#pragma unroll
        for (int o = 0; o < NORI; o++) {
            float wgt = __ldg(Whog + d * NORI + o);
            float4 hv = *(const float4*)(hw + (long)o * NPIX);
            out[0] += wgt * hv.x; out[1] += wgt * hv.y;
            out[2] += wgt * hv.z; out[3] += wgt * hv.w;
        }
    }
    *(float4*)(g_qkvdw + (long)plane * NPIX + pix) =
        make_float4(out[0], out[1], out[2], out[3]);

    if (ch < 2 * CHN) {
        float ss = out[0]*out[0] + out[1]*out[1] + out[2]*out[2] + out[3]*out[3];
#pragma unroll
        for (int o = 16; o > 0; o >>= 1) ss += __shfl_down_sync(0xffffffffu, ss, o);
        __shared__ float red[8];
        if (threadIdx.x == 0) red[threadIdx.y] = ss;
        __syncthreads();
        if (threadIdx.y == 0 && threadIdx.x == 0) {
            float s = 0.f;
#pragma unroll
            for (int i = 0; i < 8; i++) s += red[i];
            int which = ch / CHN;
            int r = which * (BATCH * CHN) + b * CHN + (ch - which * CHN);
            g_normp[r * 16 + blockIdx.y] = s;
        }
    }
}

// ============================================================
// reduce 16 partials per row -> sqrt -> g_norms. 3072 entries.
// ============================================================
__global__ __launch_bounds__(256)
void norm_reduce_kernel()
{
    int r = blockIdx.x * 256 + threadIdx.x;
    if (r >= 2 * BATCH * CHN) return;
    float s = 0.f;
#pragma unroll
    for (int i = 0; i < 16; i++) s += g_normp[r * 16 + i];
    g_norms[r] = sqrtf(s);
}

// ============================================================
// attn partial: S[bh,split][c][d] = sum_{n in split} q[c,n]*k[d,n]
// ============================================================
__global__ __launch_bounds__(256)
void attn_partial_kernel()
{
    const int bh = blockIdx.x;
    const int split = blockIdx.y;
    const int b = bh >> 2, hh = bh & 3;
    const float* Q  = g_qkvdw + ((long)b * CH3 + hh * HDIM) * NPIX;
    const float* Kp = g_qkvdw + ((long)b * CH3 + CHN + hh * HDIM) * NPIX;
    __shared__ float Qs[32][HDIM + 1];
    __shared__ float Ks[32][HDIM + 1];
    const int t = threadIdx.x;
    const int ty = t >> 4, tx = t & 15;
    float acc[3][3];
#pragma unroll
    for (int i = 0; i < 3; i++)
#pragma unroll
        for (int j = 0; j < 3; j++) acc[i][j] = 0.f;

    const int nbase = split * SPLITLEN;
    for (int chunk = 0; chunk < SPLITLEN; chunk += 32) {
#pragma unroll
        for (int i = 0; i < 6; i++) {
            int e = t + i * 256;
            int c = e >> 5, kk = e & 31;
            Qs[kk][c] = Q [(long)c * NPIX + nbase + chunk + kk];
            Ks[kk][c] = Kp[(long)c * NPIX + nbase + chunk + kk];
        }
        __syncthreads();
#pragma unroll
        for (int kk = 0; kk < 32; kk++) {
            float q0 = Qs[kk][ty*3+0], q1 = Qs[kk][ty*3+1], q2 = Qs[kk][ty*3+2];
            float c0 = Ks[kk][tx*3+0], c1 = Ks[kk][tx*3+1], c2 = Ks[kk][tx*3+2];
            acc[0][0] += q0*c0; acc[0][1] += q0*c1; acc[0][2] += q0*c2;
            acc[1][0] += q1*c0; acc[1][1] += q1*c1; acc[1][2] += q1*c2;
            acc[2][0] += q2*c0; acc[2][1] += q2*c1; acc[2][2] += q2*c2;
        }
        __syncthreads();
    }
    float* dst = g_attnp + ((long)bh * NSPLIT + split) * HDIM * HDIM;
#pragma unroll
    for (int i = 0; i < 3; i++)
#pragma unroll
        for (int j = 0; j < 3; j++)
            dst[(ty*3 + i) * HDIM + tx*3 + j] = acc[i][j];
}

// ============================================================
// reduce splits + normalize + softmax
// ============================================================
__global__ __launch_bounds__(64)
void softmax_kernel(const float* __restrict__ temp)
{
    const int blk = blockIdx.x;
    const int c  = blk % HDIM;
    const int bh = blk / HDIM;
    const int b = bh >> 2, hh = bh & 3;
    const int d = threadIdx.x;
    __shared__ float red[64];
    float val = -1e30f;
    if (d < HDIM) {
        const float* p = g_attnp + (long)bh * NSPLIT * HDIM * HDIM + c * HDIM + d;
        float s = 0.f;
#pragma unroll
        for (int sp = 0; sp < NSPLIT; sp++) s += p[(long)sp * HDIM * HDIM];
        float nq = g_norms[b * CHN + hh * HDIM + c];
        float nk = g_norms[BATCH * CHN + b * CHN + hh * HDIM + d];
        val = s / (fmaxf(nq, 1e-12f) * fmaxf(nk, 1e-12f)) * __ldg(temp + hh);
    }
    red[d] = val; __syncthreads();
    for (int o = 32; o > 0; o >>= 1) { if (d < o) red[d] = fmaxf(red[d], red[d + o]); __syncthreads(); }
    float mx = red[0]; __syncthreads();
    float e = (d < HDIM) ? expf(val - mx) : 0.f;
    red[d] = e; __syncthreads();
    for (int o = 32; o > 0; o >>= 1) { if (d < o) red[d] += red[d + o]; __syncthreads(); }
    if (d < HDIM)
        g_attn[(long)bh * HDIM * HDIM + c * HDIM + d] = e / red[0];
}

// ============================================================
// Fold W_proj with block-diagonal attn
// ============================================================
__global__ __launch_bounds__(256)
void wf_kernel(const float* __restrict__ Wproj)
{
    const int b = blockIdx.x, hh = blockIdx.y;
    __shared__ float at[HDIM][HDIM];
    const int t = threadIdx.x;
    for (int i = t; i < HDIM * HDIM; i += 256)
        at[i / HDIM][i % HDIM] = g_attn[(long)(b * NHEADS + hh) * HDIM * HDIM + i];
    __syncthreads();
    for (int i = t; i < CHN * HDIM; i += 256) {
        int e = i / HDIM, d = i - e * HDIM;
        const float* wp = Wproj + (long)e * CHN + hh * HDIM;
        float acc = 0.f;
#pragma unroll
        for (int c2 = 0; c2 < HDIM; c2++) acc += __ldg(wp + c2) * at[c2][d];
        g_wf[((long)b * CHN + e) * CHN + hh * HDIM + d] = acc;
    }
}

// ============================================================
extern "C" void kernel_launch(void* const* d_in, const int* in_sizes, int n_in,
                              void* d_out, int out_size)
{
    const float* x     = (const float*)d_in[0];
    const float* Wqkv  = (const float*)d_in[1];
    const float* Wdw   = (const float*)d_in[2];
    const float* Whog  = (const float*)d_in[3];
    const float* Wproj = (const float*)d_in[4];
    const float* temp  = (const float*)d_in[5];
    float* out = (float*)d_out;

    void *p_qkv, *p_qkvdw, *p_wf;
    cudaGetSymbolAddress(&p_qkv,   g_qkv);
    cudaGetSymbolAddress(&p_qkvdw, g_qkvdw);
    cudaGetSymbolAddress(&p_wf,    g_wf);

    // 1) qkv = W_qkv @ x     (M=576, K=192, N=16384 per batch)
    gemm_tf32_kernel<<<dim3(NPIX / 128, CH3 / 64, BATCH), 256>>>(
        Wqkv, 0L,
        x, (long)CHN * NPIX,
        (float*)p_qkv, (long)CH3 * NPIX,
        NPIX, CHN);

    // 2) Sobel + HOG bin weights
    sobel_hog_kernel<<<dim3(IMH, BATCH), 128>>>(x);

    // 3) depthwise 3x3 (+hog add on v, +norm partials on q/k)
    dwconv_hog_kernel<<<dim3(1, IMH / 8, BATCH * CH3), dim3(32, 8)>>>(Wdw, Whog);

    // 4) reduce norm partials
    norm_reduce_kernel<<<(2 * BATCH * CHN + 255) / 256, 256>>>();

    // 5) q.k^T partial dots (split-K)
    attn_partial_kernel<<<dim3(BATCH * NHEADS, NSPLIT), 256>>>();

    // 6) reduce + scale + softmax
    softmax_kernel<<<BATCH * NHEADS * HDIM, 64>>>(temp);

    // 7) fold W_proj with attn -> per-batch 192x192
    wf_kernel<<<dim3(BATCH, NHEADS), 256>>>(Wproj);

    // 8) out = Wf @ v         (M=192, K=192, N=16384 per batch)
    gemm_tf32_kernel<<<dim3(NPIX / 128, CHN / 64, BATCH), 256>>>(
        (const float*)p_wf, (long)CHN * CHN,
        (const float*)p_qkvdw + (long)2 * CHN * NPIX, (long)CH3 * NPIX,
        out, (long)CHN * NPIX,
        NPIX, CHN);
}

// round 5
// speedup vs baseline: 1.4642x; 1.2181x over previous
#include <cuda_runtime.h>
#include <math.h>
#include <stdint.h>

#define BATCH 8
#define CHN 192
#define CH3 576
#define IMH 128
#define IMW 128
#define NPIX (IMH*IMW)         // 16384
#define NHEADS 4
#define HDIM 48
#define NORI 9
#define NSPLIT 32
#define SPLITLEN (NPIX/NSPLIT) // 512
#define PI_F 3.14159265358979323846f
#define NB 4                   // pipeline buffers (lookahead 2)

// ---- device scratch (no allocation allowed) ----
__device__ float g_qkv  [BATCH*CH3*NPIX];
__device__ float g_qkvdw[BATCH*CH3*NPIX];
__device__ float g_hogw [BATCH*NORI*NPIX];
__device__ float g_normp[2*BATCH*CHN*16];
__device__ float g_norms[2*BATCH*CHN];
__device__ float g_attnp[BATCH*NHEADS*NSPLIT*HDIM*HDIM];
__device__ float g_attn [BATCH*NHEADS*HDIM*HDIM];
__device__ float g_wf   [BATCH*CHN*CHN];

__device__ __forceinline__ unsigned f2tf32(float x) {
    unsigned r;
    asm("cvt.rna.tf32.f32 %0, %1;" : "=r"(r) : "f"(x));
    return r;
}
__device__ __forceinline__ uint32_t smem_u32(const void* p) {
    return (uint32_t)__cvta_generic_to_shared(p);
}
__device__ __forceinline__ void cp_async16(uint32_t dst, const void* src) {
    asm volatile("cp.async.cg.shared.global [%0], [%1], 16;\n" :: "r"(dst), "l"(src));
}
__device__ __forceinline__ void cp_commit() {
    asm volatile("cp.async.commit_group;\n");
}
__device__ __forceinline__ void cp_wait2() {
    asm volatile("cp.async.wait_group 2;\n");
}

#define MMA_TF32(d, a, b) \
    asm volatile( \
        "mma.sync.aligned.m16n8k8.row.col.f32.tf32.tf32.f32 " \
        "{%0,%1,%2,%3}, {%4,%5,%6,%7}, {%8,%9}, {%0,%1,%2,%3};\n" \
        : "+f"((d)[0]), "+f"((d)[1]), "+f"((d)[2]), "+f"((d)[3]) \
        : "r"((a)[0]), "r"((a)[1]), "r"((a)[2]), "r"((a)[3]), \
          "r"((b)[0]), "r"((b)[1]))

// ============================================================
// tf32 GEMM: C[z](MxN) = A[z](MxK) * B[z](KxN). BM=64 BN=256 BK=16.
// 256 thr (8 warps, 2x4), warp tile 32x64 (mt=2, nt=8).
// 4-buffer cp.async pipeline, ONE barrier per k-iter.
// As [m][k] stride 20, Bs [k][n] stride 264 (both conflict-free).
// dyn smem = NB*(64*20 + 16*264)*4 = 88064 B. M%64==0, N%256==0, K%16==0.
// ============================================================
#define ASZ (64*20)
#define BSZ (16*264)
__global__ __launch_bounds__(256, 2)
void gemm_tf32_kernel(const float* __restrict__ A, long sA,
                      const float* __restrict__ B, long sB,
                      float* __restrict__ Cm, long sC,
                      int N, int K)
{
    extern __shared__ float smem[];
    float* As = smem;             // NB stages of 64x20
    float* Bs = smem + NB * ASZ;  // NB stages of 16x264

    const int t = threadIdx.x;
    const int lane = t & 31;
    const int warp = t >> 5;
    const int wm = warp >> 2;        // 0..1
    const int wn = warp & 3;         // 0..3
    const int m0 = blockIdx.y * 64;
    const int n0 = blockIdx.x * 256;
    const float* Ab = A + (long)blockIdx.z * sA;
    const float* Bb = B + (long)blockIdx.z * sB;
    float*       Cb = Cm + (long)blockIdx.z * sC;

    const int am = t >> 2;           // 0..63
    const int ac = t & 3;
    const int brow = t >> 4;         // 0..15
    const int bch  = t & 15;         // 16B chunk base
    const int kc = lane & 3;
    const int lq = lane >> 2;

    const int niter = K / 16;

    float acc[2][8][4];
#pragma unroll
    for (int i = 0; i < 2; i++)
#pragma unroll
        for (int j = 0; j < 8; j++)
#pragma unroll
            for (int r = 0; r < 4; r++) acc[i][j][r] = 0.f;

    auto issue_stage = [&](int it) {
        const int stg = it & (NB - 1);
        const int k0 = it * 16;
        cp_async16(smem_u32(&As[stg * ASZ + am * 20 + ac * 4]),
                   Ab + (long)(m0 + am) * K + k0 + ac * 4);
#pragma unroll
        for (int j = 0; j < 4; j++) {
            int c4 = bch + 16 * j;
            cp_async16(smem_u32(&Bs[stg * BSZ + brow * 264 + c4 * 4]),
                       Bb + (long)(k0 + brow) * N + n0 + c4 * 4);
        }
    };

#pragma unroll
    for (int s = 0; s < 2; s++) {
        if (s < niter) issue_stage(s);
        cp_commit();
    }

    for (int it = 0; it < niter; it++) {
        if (it + 2 < niter) issue_stage(it + 2);
        cp_commit();
        cp_wait2();
        __syncthreads();

        const float* Ast = As + (it & (NB - 1)) * ASZ;
        const float* Bst = Bs + (it & (NB - 1)) * BSZ;

#pragma unroll
        for (int kk = 0; kk < 2; kk++) {
            const int kb = kk * 8;
            unsigned af[2][4], bf[8][2];
#pragma unroll
            for (int mt = 0; mt < 2; mt++) {
                int r = wm * 32 + mt * 16 + lq;
                af[mt][0] = f2tf32(Ast[r * 20 + kb + kc]);
                af[mt][1] = f2tf32(Ast[(r + 8) * 20 + kb + kc]);
                af[mt][2] = f2tf32(Ast[r * 20 + kb + kc + 4]);
                af[mt][3] = f2tf32(Ast[(r + 8) * 20 + kb + kc + 4]);
            }
#pragma unroll
            for (int nt = 0; nt < 8; nt++) {
                int c = wn * 64 + nt * 8 + lq;
                bf[nt][0] = f2tf32(Bst[(kb + kc) * 264 + c]);
                bf[nt][1] = f2tf32(Bst[(kb + kc + 4) * 264 + c]);
            }
#pragma unroll
            for (int mt = 0; mt < 2; mt++)
#pragma unroll
                for (int nt = 0; nt < 8; nt++)
                    MMA_TF32(acc[mt][nt], af[mt], bf[nt]);
        }
    }

#pragma unroll
    for (int mt = 0; mt < 2; mt++) {
        int r = m0 + wm * 32 + mt * 16 + lq;
#pragma unroll
        for (int nt = 0; nt < 8; nt++) {
            int c = n0 + wn * 64 + nt * 8 + kc * 2;
            *(float2*)(Cb + (long)r * N + c) =
                make_float2(acc[mt][nt][0], acc[mt][nt][1]);
            *(float2*)(Cb + (long)(r + 8) * N + c) =
                make_float2(acc[mt][nt][2], acc[mt][nt][3]);
        }
    }
}

// ============================================================
// attn partial via tf32 MMA: S[bh,split][48][48] = Q_tile @ K_tile^T.
// 192 thr (6 warps: wm 0..2 m16, wn 0..1 n24). Contraction = 512 px,
// chunks of 32. 4-buffer cp.async, one barrier per chunk.
// Qs/Ks [chan][px] stride 36 (conflict-free). dyn smem = 55296 B.
// ============================================================
#define QSZ (48*36)
__global__ __launch_bounds__(192, 4)
void attn_partial_kernel()
{
    extern __shared__ float smem[];
    float* Qs = smem;             // NB stages 48x36
    float* Ks = smem + NB * QSZ;

    const int bh = blockIdx.x;
    const int split = blockIdx.y;
    const int b = bh >> 2, hh = bh & 3;
    const float* Qg = g_qkvdw + ((long)b * CH3 + hh * HDIM) * NPIX;
    const float* Kg = g_qkvdw + ((long)b * CH3 + CHN + hh * HDIM) * NPIX;
    const int nbase = split * SPLITLEN;

    const int t = threadIdx.x;
    const int lane = t & 31;
    const int warp = t >> 5;
    const int wm = warp % 3;          // m tile: 16 rows
    const int wn = warp / 3;          // n tile: 24 cols
    const int kc = lane & 3;
    const int lq = lane >> 2;

    float acc[3][4];
#pragma unroll
    for (int i = 0; i < 3; i++)
#pragma unroll
        for (int r = 0; r < 4; r++) acc[i][r] = 0.f;

    const int niter = SPLITLEN / 32;   // 16 chunks of 32 px

    auto issue_stage = [&](int it) {
        const int stg = it & (NB - 1);
        const int base = nbase + it * 32;
#pragma unroll
        for (int j = 0; j < 2; j++) {
            int idx = t + 192 * j;          // 0..383
            int r = idx >> 3, c4 = idx & 7; // chan, 16B chunk
            cp_async16(smem_u32(&Qs[stg * QSZ + r * 36 + c4 * 4]),
                       Qg + (long)r * NPIX + base + c4 * 4);
            cp_async16(smem_u32(&Ks[stg * QSZ + r * 36 + c4 * 4]),
                       Kg + (long)r * NPIX + base + c4 * 4);
        }
    };

#pragma unroll
    for (int s = 0; s < 2; s++) {
        if (s < niter) issue_stage(s);
        cp_commit();
    }

    for (int it = 0; it < niter; it++) {
        if (it + 2 < niter) issue_stage(it + 2);
        cp_commit();
        cp_wait2();
        __syncthreads();

        const float* Qst = Qs + (it & (NB - 1)) * QSZ;
        const float* Kst = Ks + (it & (NB - 1)) * QSZ;

#pragma unroll
        for (int k8 = 0; k8 < 4; k8++) {
            const int kb = k8 * 8;
            unsigned af[4], bf[3][2];
            int r = wm * 16 + lq;
            af[0] = f2tf32(Qst[r * 36 + kb + kc]);
            af[1] = f2tf32(Qst[(r + 8) * 36 + kb + kc]);
            af[2] = f2tf32(Qst[r * 36 + kb + kc + 4]);
            af[3] = f2tf32(Qst[(r + 8) * 36 + kb + kc + 4]);
#pragma unroll
            for (int nt = 0; nt < 3; nt++) {
                int c = wn * 24 + nt * 8 + lq;
                bf[nt][0] = f2tf32(Kst[c * 36 + kb + kc]);
                bf[nt][1] = f2tf32(Kst[c * 36 + kb + kc + 4]);
            }
#pragma unroll
            for (int nt = 0; nt < 3; nt++)
                MMA_TF32(acc[nt], af, bf[nt]);
        }
    }

    float* dst = g_attnp + ((long)bh * NSPLIT + split) * HDIM * HDIM;
    int row = wm * 16 + lq;
#pragma unroll
    for (int nt = 0; nt < 3; nt++) {
        int col = wn * 24 + nt * 8 + kc * 2;
        *(float2*)(dst + row * HDIM + col) = make_float2(acc[nt][0], acc[nt][1]);
        *(float2*)(dst + (row + 8) * HDIM + col) = make_float2(acc[nt][2], acc[nt][3]);
    }
}

// ============================================================
// Sobel (replicate pad, /8 kernels) -> channel-mean mag/ang -> HOG weights
// ============================================================
__global__ __launch_bounds__(128)
void sobel_hog_kernel(const float* __restrict__ x)
{
    const int w = threadIdx.x;
    const int h = blockIdx.x;
    const int b = blockIdx.y;
    const int hm = h > 0 ? h - 1 : 0;
    const int hp = h < IMH - 1 ? h + 1 : IMH - 1;
    const int wm = w > 0 ? w - 1 : 0;
    const int wp = w < IMW - 1 ? w + 1 : IMW - 1;
    const float* xb = x + (long)b * CHN * NPIX;

    float msum = 0.f, asum = 0.f;
    for (int c = 0; c < CHN; c++) {
        const float* p = xb + (long)c * NPIX;
        float a00 = __ldg(p + hm*IMW + wm), a01 = __ldg(p + hm*IMW + w), a02 = __ldg(p + hm*IMW + wp);
        float a10 = __ldg(p + h *IMW + wm),                              a12 = __ldg(p + h *IMW + wp);
        float a20 = __ldg(p + hp*IMW + wm), a21 = __ldg(p + hp*IMW + w), a22 = __ldg(p + hp*IMW + wp);
        float dx = (a02 - a00 + 2.f*(a12 - a10) + a22 - a20) * 0.125f;
        float dy = (a20 - a00 + 2.f*(a21 - a01) + a22 - a02) * 0.125f;
        msum += sqrtf(dx*dx + dy*dy + 1e-6f);
        asum += atan2f(dy, dx + 1e-6f);
    }
    float mag = msum * (1.f / CHN);
    float ang = asum * (1.f / CHN);
    ang = ang - PI_F * floorf(ang / PI_F);
    const float binw = PI_F / NORI;
    const int pix = h * IMW + w;
#pragma unroll
    for (int o = 0; o < NORI; o++) {
        float cen = ((float)o + 0.5f) * binw;
        float wgt = 1.f - fabsf(ang - cen) / binw;
        wgt = wgt > 0.f ? wgt : 0.f;
        g_hogw[((long)b * NORI + o) * NPIX + pix] = wgt * mag;
    }
}

// ============================================================
// Depthwise 3x3 SAME (zero pad), 4 px/thread, fused HOG add on v channels,
// fused sum-of-squares partials for q/k channels.
// ============================================================
__global__ __launch_bounds__(256)
void dwconv_hog_kernel(const float* __restrict__ Wdw, const float* __restrict__ Whog)
{
    const int plane = blockIdx.z;
    const int b  = plane / CH3;
    const int ch = plane - b * CH3;
    const int w0 = threadIdx.x * 4;
    const int h  = blockIdx.y * 8 + threadIdx.y;
    const float* in = g_qkv + (long)plane * NPIX;
    const float* kw = Wdw + ch * 9;
    float k0 = __ldg(kw+0), k1 = __ldg(kw+1), k2 = __ldg(kw+2);
    float k3 = __ldg(kw+3), k4 = __ldg(kw+4), k5 = __ldg(kw+5);
    float k6 = __ldg(kw+6), k7 = __ldg(kw+7), k8 = __ldg(kw+8);

    float row[3][6];
#pragma unroll
    for (int rr = 0; rr < 3; rr++) {
        int hh = h + rr - 1;
        if (hh >= 0 && hh < IMH) {
            const float* p = in + hh * IMW + w0;
            float4 cv = *(const float4*)p;
            row[rr][1] = cv.x; row[rr][2] = cv.y; row[rr][3] = cv.z; row[rr][4] = cv.w;
            row[rr][0] = (w0 > 0)       ? __ldg(p - 1) : 0.f;
            row[rr][5] = (w0 + 4 < IMW) ? __ldg(p + 4) : 0.f;
        } else {
#pragma unroll
            for (int j = 0; j < 6; j++) row[rr][j] = 0.f;
        }
    }

    float out[4];
#pragma unroll
    for (int j = 0; j < 4; j++) {
        out[j] = k0*row[0][j] + k1*row[0][j+1] + k2*row[0][j+2]
               + k3*row[1][j] + k4*row[1][j+1] + k5*row[1][j+2]
               + k6*row[2][j] + k7*row[2][j+1] + k8*row[2][j+2];
    }

    const int pix = h * IMW + w0;
    if (ch >= 2 * CHN) {
        int d = ch - 2 * CHN;
        const float* hw = g_hogw + (long)b * NORI * NPIX + pix;
#pragma unroll
        for (int o = 0; o < NORI; o++) {
            float wgt = __ldg(Whog + d * NORI + o);
            float4 hv = *(const float4*)(hw + (long)o * NPIX);
            out[0] += wgt * hv.x; out[1] += wgt * hv.y;
            out[2] += wgt * hv.z; out[3] += wgt * hv.w;
        }
    }
    *(float4*)(g_qkvdw + (long)plane * NPIX + pix) =
        make_float4(out[0], out[1], out[2], out[3]);

    if (ch < 2 * CHN) {
        float ss = out[0]*out[0] + out[1]*out[1] + out[2]*out[2] + out[3]*out[3];
#pragma unroll
        for (int o = 16; o > 0; o >>= 1) ss += __shfl_down_sync(0xffffffffu, ss, o);
        __shared__ float red[8];
        if (threadIdx.x == 0) red[threadIdx.y] = ss;
        __syncthreads();
        if (threadIdx.y == 0 && threadIdx.x == 0) {
            float s = 0.f;
#pragma unroll
            for (int i = 0; i < 8; i++) s += red[i];
            int which = ch / CHN;
            int r = which * (BATCH * CHN) + b * CHN + (ch - which * CHN);
            g_normp[r * 16 + blockIdx.y] = s;
        }
    }
}

// ============================================================
__global__ __launch_bounds__(256)
void norm_reduce_kernel()
{
    int r = blockIdx.x * 256 + threadIdx.x;
    if (r >= 2 * BATCH * CHN) return;
    float s = 0.f;
#pragma unroll
    for (int i = 0; i < 16; i++) s += g_normp[r * 16 + i];
    g_norms[r] = sqrtf(s);
}

// ============================================================
// reduce splits + normalize + softmax
// ============================================================
__global__ __launch_bounds__(64)
void softmax_kernel(const float* __restrict__ temp)
{
    const int blk = blockIdx.x;
    const int c  = blk % HDIM;
    const int bh = blk / HDIM;
    const int b = bh >> 2, hh = bh & 3;
    const int d = threadIdx.x;
    __shared__ float red[64];
    float val = -1e30f;
    if (d < HDIM) {
        const float* p = g_attnp + (long)bh * NSPLIT * HDIM * HDIM + c * HDIM + d;
        float s = 0.f;
#pragma unroll
        for (int sp = 0; sp < NSPLIT; sp++) s += p[(long)sp * HDIM * HDIM];
        float nq = g_norms[b * CHN + hh * HDIM + c];
        float nk = g_norms[BATCH * CHN + b * CHN + hh * HDIM + d];
        val = s / (fmaxf(nq, 1e-12f) * fmaxf(nk, 1e-12f)) * __ldg(temp + hh);
    }
    red[d] = val; __syncthreads();
    for (int o = 32; o > 0; o >>= 1) { if (d < o) red[d] = fmaxf(red[d], red[d + o]); __syncthreads(); }
    float mx = red[0]; __syncthreads();
    float e = (d < HDIM) ? expf(val - mx) : 0.f;
    red[d] = e; __syncthreads();
    for (int o = 32; o > 0; o >>= 1) { if (d < o) red[d] += red[d + o]; __syncthreads(); }
    if (d < HDIM)
        g_attn[(long)bh * HDIM * HDIM + c * HDIM + d] = e / red[0];
}

// ============================================================
// Fold W_proj with block-diagonal attn
// ============================================================
__global__ __launch_bounds__(256)
void wf_kernel(const float* __restrict__ Wproj)
{
    const int b = blockIdx.x, hh = blockIdx.y;
    __shared__ float at[HDIM][HDIM];
    const int t = threadIdx.x;
    for (int i = t; i < HDIM * HDIM; i += 256)
        at[i / HDIM][i % HDIM] = g_attn[(long)(b * NHEADS + hh) * HDIM * HDIM + i];
    __syncthreads();
    for (int i = t; i < CHN * HDIM; i += 256) {
        int e = i / HDIM, d = i - e * HDIM;
        const float* wp = Wproj + (long)e * CHN + hh * HDIM;
        float acc = 0.f;
#pragma unroll
        for (int c2 = 0; c2 < HDIM; c2++) acc += __ldg(wp + c2) * at[c2][d];
        g_wf[((long)b * CHN + e) * CHN + hh * HDIM + d] = acc;
    }
}

// ============================================================
extern "C" void kernel_launch(void* const* d_in, const int* in_sizes, int n_in,
                              void* d_out, int out_size)
{
    const float* x     = (const float*)d_in[0];
    const float* Wqkv  = (const float*)d_in[1];
    const float* Wdw   = (const float*)d_in[2];
    const float* Whog  = (const float*)d_in[3];
    const float* Wproj = (const float*)d_in[4];
    const float* temp  = (const float*)d_in[5];
    float* out = (float*)d_out;

    void *p_qkv, *p_qkvdw, *p_wf;
    cudaGetSymbolAddress(&p_qkv,   g_qkv);
    cudaGetSymbolAddress(&p_qkvdw, g_qkvdw);
    cudaGetSymbolAddress(&p_wf,    g_wf);

    const int gemm_smem = NB * (ASZ + BSZ) * 4;   // 88064
    const int attn_smem = 2 * NB * QSZ * 4;       // 55296
    cudaFuncSetAttribute(gemm_tf32_kernel,
                         cudaFuncAttributeMaxDynamicSharedMemorySize, gemm_smem);
    cudaFuncSetAttribute(attn_partial_kernel,
                         cudaFuncAttributeMaxDynamicSharedMemorySize, attn_smem);

    // 1) qkv = W_qkv @ x     (M=576, K=192, N=16384 per batch)
    gemm_tf32_kernel<<<dim3(NPIX / 256, CH3 / 64, BATCH), 256, gemm_smem>>>(
        Wqkv, 0L,
        x, (long)CHN * NPIX,
        (float*)p_qkv, (long)CH3 * NPIX,
        NPIX, CHN);

    // 2) Sobel + HOG bin weights
    sobel_hog_kernel<<<dim3(IMH, BATCH), 128>>>(x);

    // 3) depthwise 3x3 (+hog add on v, +norm partials on q/k)
    dwconv_hog_kernel<<<dim3(1, IMH / 8, BATCH * CH3), dim3(32, 8)>>>(Wdw, Whog);

    // 4) reduce norm partials
    norm_reduce_kernel<<<(2 * BATCH * CHN + 255) / 256, 256>>>();

    // 5) q.k^T partial dots (split-K) — tf32 MMA
    attn_partial_kernel<<<dim3(BATCH * NHEADS, NSPLIT), 192, attn_smem>>>();

    // 6) reduce + scale + softmax
    softmax_kernel<<<BATCH * NHEADS * HDIM, 64>>>(temp);

    // 7) fold W_proj with attn -> per-batch 192x192
    wf_kernel<<<dim3(BATCH, NHEADS), 256>>>(Wproj);

    // 8) out = Wf @ v         (M=192, K=192, N=16384 per batch)
    gemm_tf32_kernel<<<dim3(NPIX / 256, CHN / 64, BATCH), 256, gemm_smem>>>(
        (const float*)p_wf, (long)CHN * CHN,
        (const float*)p_qkvdw + (long)2 * CHN * NPIX, (long)CH3 * NPIX,
        out, (long)CHN * NPIX,
        NPIX, CHN);
}

// round 7
// speedup vs baseline: 1.5737x; 1.0748x over previous
#include <cuda_runtime.h>
#include <math.h>
#include <stdint.h>

#define BATCH 8
#define CHN 192
#define CH3 576
#define IMH 128
#define IMW 128
#define NPIX (IMH*IMW)         // 16384
#define NHEADS 4
#define HDIM 48
#define NORI 9
#define NSPLIT 32
#define SPLITLEN (NPIX/NSPLIT) // 512
#define PI_F 3.14159265358979323846f
#define NB 4                   // pipeline buffers (lookahead 2)

// ---- device scratch (no allocation allowed) ----
__device__ float g_qkv  [BATCH*CH3*NPIX];
__device__ float g_qkvdw[BATCH*CH3*NPIX];
__device__ float g_hogw [BATCH*NORI*NPIX];
__device__ float g_normp[2*BATCH*CHN*16];
__device__ float g_norms[2*BATCH*CHN];
__device__ float g_attnp[BATCH*NHEADS*NSPLIT*HDIM*HDIM];
__device__ float g_attn [BATCH*NHEADS*HDIM*HDIM];
__device__ float g_wf   [BATCH*CHN*CHN];

// round-to-nearest tf32 conversion (REQUIRED: truncation biases the K-sum
// and pushed rel_err to 1.5e-3 in round 6)
__device__ __forceinline__ unsigned f2tf32(float x) {
    unsigned r;
    asm("cvt.rna.tf32.f32 %0, %1;" : "=r"(r) : "f"(x));
    return r;
}
__device__ __forceinline__ uint32_t smem_u32(const void* p) {
    return (uint32_t)__cvta_generic_to_shared(p);
}
__device__ __forceinline__ void cp_async16(uint32_t dst, const void* src) {
    asm volatile("cp.async.cg.shared.global [%0], [%1], 16;\n" :: "r"(dst), "l"(src));
}
__device__ __forceinline__ void cp_commit() {
    asm volatile("cp.async.commit_group;\n");
}
__device__ __forceinline__ void cp_wait2() {
    asm volatile("cp.async.wait_group 2;\n");
}
__device__ __forceinline__ float fast_sqrtf(float x) {
    float r; asm("sqrt.approx.f32 %0, %1;" : "=f"(r) : "f"(x)); return r;
}
// atan2 via odd polynomial on [0,1]; max err ~1e-5 rad.
__device__ __forceinline__ float fast_atan2f(float y, float x) {
    float ax = fabsf(x), ay = fabsf(y);
    float mx = fmaxf(ax, ay), mn = fminf(ax, ay);
    float a = __fdividef(mn, mx);
    float s = a * a;
    float r = -0.0117212f;
    r = fmaf(r, s,  0.05265332f);
    r = fmaf(r, s, -0.11643287f);
    r = fmaf(r, s,  0.19354346f);
    r = fmaf(r, s, -0.33262347f);
    r = fmaf(r, s,  0.99997726f);
    r = r * a;
    if (ay > ax) r = 1.57079632679f - r;
    if (x < 0.f) r = PI_F - r;
    return y < 0.f ? -r : r;
}

#define MMA_TF32(d, a, b) \
    asm volatile( \
        "mma.sync.aligned.m16n8k8.row.col.f32.tf32.tf32.f32 " \
        "{%0,%1,%2,%3}, {%4,%5,%6,%7}, {%8,%9}, {%0,%1,%2,%3};\n" \
        : "+f"((d)[0]), "+f"((d)[1]), "+f"((d)[2]), "+f"((d)[3]) \
        : "r"((a)[0]), "r"((a)[1]), "r"((a)[2]), "r"((a)[3]), \
          "r"((b)[0]), "r"((b)[1]))

// ============================================================
// tf32 GEMM: C[z](MxN) = A[z](MxK) * B[z](KxN). BM=64 BN=256 BK=16.
// 256 thr (8 warps, 2x4), warp tile 32x64 (mt=2, nt=8).
// 4-buffer cp.async pipeline, ONE barrier per k-iter.
// As [m][k] stride 20, Bs [k][n] stride 264 (both conflict-free).
// dyn smem = NB*(64*20 + 16*264)*4 = 88064 B. M%64==0, N%256==0, K%16==0.
// ============================================================
#define ASZ (64*20)
#define BSZ (16*264)
__global__ __launch_bounds__(256, 2)
void gemm_tf32_kernel(const float* __restrict__ A, long sA,
                      const float* __restrict__ B, long sB,
                      float* __restrict__ Cm, long sC,
                      int N, int K)
{
    extern __shared__ float smem[];
    float* As = smem;             // NB stages of 64x20
    float* Bs = smem + NB * ASZ;  // NB stages of 16x264

    const int t = threadIdx.x;
    const int lane = t & 31;
    const int warp = t >> 5;
    const int wm = warp >> 2;        // 0..1
    const int wn = warp & 3;         // 0..3
    const int m0 = blockIdx.y * 64;
    const int n0 = blockIdx.x * 256;
    const float* Ab = A + (long)blockIdx.z * sA;
    const float* Bb = B + (long)blockIdx.z * sB;
    float*       Cb = Cm + (long)blockIdx.z * sC;

    const int am = t >> 2;           // 0..63
    const int ac = t & 3;
    const int brow = t >> 4;         // 0..15
    const int bch  = t & 15;         // 16B chunk base
    const int kc = lane & 3;
    const int lq = lane >> 2;

    const int niter = K / 16;

    float acc[2][8][4];
#pragma unroll
    for (int i = 0; i < 2; i++)
#pragma unroll
        for (int j = 0; j < 8; j++)
#pragma unroll
            for (int r = 0; r < 4; r++) acc[i][j][r] = 0.f;

    auto issue_stage = [&](int it) {
        const int stg = it & (NB - 1);
        const int k0 = it * 16;
        cp_async16(smem_u32(&As[stg * ASZ + am * 20 + ac * 4]),
                   Ab + (long)(m0 + am) * K + k0 + ac * 4);
#pragma unroll
        for (int j = 0; j < 4; j++) {
            int c4 = bch + 16 * j;
            cp_async16(smem_u32(&Bs[stg * BSZ + brow * 264 + c4 * 4]),
                       Bb + (long)(k0 + brow) * N + n0 + c4 * 4);
        }
    };

#pragma unroll
    for (int s = 0; s < 2; s++) {
        if (s < niter) issue_stage(s);
        cp_commit();
    }

    for (int it = 0; it < niter; it++) {
        if (it + 2 < niter) issue_stage(it + 2);
        cp_commit();
        cp_wait2();
        __syncthreads();

        const float* Ast = As + (it & (NB - 1)) * ASZ;
        const float* Bst = Bs + (it & (NB - 1)) * BSZ;

#pragma unroll
        for (int kk = 0; kk < 2; kk++) {
            const int kb = kk * 8;
            unsigned af[2][4], bf[8][2];
#pragma unroll
            for (int mt = 0; mt < 2; mt++) {
                int r = wm * 32 + mt * 16 + lq;
                af[mt][0] = f2tf32(Ast[r * 20 + kb + kc]);
                af[mt][1] = f2tf32(Ast[(r + 8) * 20 + kb + kc]);
                af[mt][2] = f2tf32(Ast[r * 20 + kb + kc + 4]);
                af[mt][3] = f2tf32(Ast[(r + 8) * 20 + kb + kc + 4]);
            }
#pragma unroll
            for (int nt = 0; nt < 8; nt++) {
                int c = wn * 64 + nt * 8 + lq;
                bf[nt][0] = f2tf32(Bst[(kb + kc) * 264 + c]);
                bf[nt][1] = f2tf32(Bst[(kb + kc + 4) * 264 + c]);
            }
#pragma unroll
            for (int mt = 0; mt < 2; mt++)
#pragma unroll
                for (int nt = 0; nt < 8; nt++)
                    MMA_TF32(acc[mt][nt], af[mt], bf[nt]);
        }
    }

#pragma unroll
    for (int mt = 0; mt < 2; mt++) {
        int r = m0 + wm * 32 + mt * 16 + lq;
#pragma unroll
        for (int nt = 0; nt < 8; nt++) {
            int c = n0 + wn * 64 + nt * 8 + kc * 2;
            *(float2*)(Cb + (long)r * N + c) =
                make_float2(acc[mt][nt][0], acc[mt][nt][1]);
            *(float2*)(Cb + (long)(r + 8) * N + c) =
                make_float2(acc[mt][nt][2], acc[mt][nt][3]);
        }
    }
}

// ============================================================
// attn partial via tf32 MMA: S[bh,split][48][48] = Q_tile @ K_tile^T.
// 192 thr (6 warps: wm 0..2 m16, wn 0..1 n24). 4-buffer cp.async.
// Qs/Ks [chan][px] stride 36. dyn smem = 55296 B.
// ============================================================
#define QSZ (48*36)
__global__ __launch_bounds__(192, 4)
void attn_partial_kernel()
{
    extern __shared__ float smem[];
    float* Qs = smem;             // NB stages 48x36
    float* Ks = smem + NB * QSZ;

    const int bh = blockIdx.x;
    const int split = blockIdx.y;
    const int b = bh >> 2, hh = bh & 3;
    const float* Qg = g_qkvdw + ((long)b * CH3 + hh * HDIM) * NPIX;
    const float* Kg = g_qkvdw + ((long)b * CH3 + CHN + hh * HDIM) * NPIX;
    const int nbase = split * SPLITLEN;

    const int t = threadIdx.x;
    const int lane = t & 31;
    const int warp = t >> 5;
    const int wm = warp % 3;          // m tile: 16 rows
    const int wn = warp / 3;          // n tile: 24 cols
    const int kc = lane & 3;
    const int lq = lane >> 2;

    float acc[3][4];
#pragma unroll
    for (int i = 0; i < 3; i++)
#pragma unroll
        for (int r = 0; r < 4; r++) acc[i][r] = 0.f;

    const int niter = SPLITLEN / 32;   // 16 chunks of 32 px

    auto issue_stage = [&](int it) {
        const int stg = it & (NB - 1);
        const int base = nbase + it * 32;
#pragma unroll
        for (int j = 0; j < 2; j++) {
            int idx = t + 192 * j;          // 0..383
            int r = idx >> 3, c4 = idx & 7;
            cp_async16(smem_u32(&Qs[stg * QSZ + r * 36 + c4 * 4]),
                       Qg + (long)r * NPIX + base + c4 * 4);
            cp_async16(smem_u32(&Ks[stg * QSZ + r * 36 + c4 * 4]),
                       Kg + (long)r * NPIX + base + c4 * 4);
        }
    };

#pragma unroll
    for (int s = 0; s < 2; s++) {
        if (s < niter) issue_stage(s);
        cp_commit();
    }

    for (int it = 0; it < niter; it++) {
        if (it + 2 < niter) issue_stage(it + 2);
        cp_commit();
        cp_wait2();
        __syncthreads();

        const float* Qst = Qs + (it & (NB - 1)) * QSZ;
        const float* Kst = Ks + (it & (NB - 1)) * QSZ;

#pragma unroll
        for (int k8 = 0; k8 < 4; k8++) {
            const int kb = k8 * 8;
            unsigned af[4], bf[3][2];
            int r = wm * 16 + lq;
            af[0] = f2tf32(Qst[r * 36 + kb + kc]);
            af[1] = f2tf32(Qst[(r + 8) * 36 + kb + kc]);
            af[2] = f2tf32(Qst[r * 36 + kb + kc + 4]);
            af[3] = f2tf32(Qst[(r + 8) * 36 + kb + kc + 4]);
#pragma unroll
            for (int nt = 0; nt < 3; nt++) {
                int c = wn * 24 + nt * 8 + lq;
                bf[nt][0] = f2tf32(Kst[c * 36 + kb + kc]);
                bf[nt][1] = f2tf32(Kst[c * 36 + kb + kc + 4]);
            }
#pragma unroll
            for (int nt = 0; nt < 3; nt++)
                MMA_TF32(acc[nt], af, bf[nt]);
        }
    }

    float* dst = g_attnp + ((long)bh * NSPLIT + split) * HDIM * HDIM;
    int row = wm * 16 + lq;
#pragma unroll
    for (int nt = 0; nt < 3; nt++) {
        int col = wn * 24 + nt * 8 + kc * 2;
        *(float2*)(dst + row * HDIM + col) = make_float2(acc[nt][0], acc[nt][1]);
        *(float2*)(dst + (row + 8) * HDIM + col) = make_float2(acc[nt][2], acc[nt][3]);
    }
}

// ============================================================
// Sobel (replicate pad, /8 kernels) -> channel-mean mag/ang -> HOG weights
// Fast polynomial atan2 + approx sqrt.
// ============================================================
__global__ __launch_bounds__(128)
void sobel_hog_kernel(const float* __restrict__ x)
{
    const int w = threadIdx.x;
    const int h = blockIdx.x;
    const int b = blockIdx.y;
    const int hm = h > 0 ? h - 1 : 0;
    const int hp = h < IMH - 1 ? h + 1 : IMH - 1;
    const int wm = w > 0 ? w - 1 : 0;
    const int wp = w < IMW - 1 ? w + 1 : IMW - 1;
    const float* xb = x + (long)b * CHN * NPIX;

    float msum = 0.f, asum = 0.f;
    for (int c = 0; c < CHN; c++) {
        const float* p = xb + (long)c * NPIX;
        float a00 = __ldg(p + hm*IMW + wm), a01 = __ldg(p + hm*IMW + w), a02 = __ldg(p + hm*IMW + wp);
        float a10 = __ldg(p + h *IMW + wm),                              a12 = __ldg(p + h *IMW + wp);
        float a20 = __ldg(p + hp*IMW + wm), a21 = __ldg(p + hp*IMW + w), a22 = __ldg(p + hp*IMW + wp);
        float dx = (a02 - a00 + 2.f*(a12 - a10) + a22 - a20) * 0.125f;
        float dy = (a20 - a00 + 2.f*(a21 - a01) + a22 - a02) * 0.125f;
        msum += fast_sqrtf(dx*dx + dy*dy + 1e-6f);
        asum += fast_atan2f(dy, dx + 1e-6f);
    }
    float mag = msum * (1.f / CHN);
    float ang = asum * (1.f / CHN);
    ang = ang - PI_F * floorf(ang / PI_F);
    const float binw = PI_F / NORI;
    const int pix = h * IMW + w;
#pragma unroll
    for (int o = 0; o < NORI; o++) {
        float cen = ((float)o + 0.5f) * binw;
        float wgt = 1.f - fabsf(ang - cen) / binw;
        wgt = wgt > 0.f ? wgt : 0.f;
        g_hogw[((long)b * NORI + o) * NPIX + pix] = wgt * mag;
    }
}

// ============================================================
// Depthwise 3x3 SAME (zero pad), 4 px/thread, fused HOG add on v channels,
// fused sum-of-squares partials for q/k channels.
// ============================================================
__global__ __launch_bounds__(256)
void dwconv_hog_kernel(const float* __restrict__ Wdw, const float* __restrict__ Whog)
{
    const int plane = blockIdx.z;
    const int b  = plane / CH3;
    const int ch = plane - b * CH3;
    const int w0 = threadIdx.x * 4;
    const int h  = blockIdx.y * 8 + threadIdx.y;
    const float* in = g_qkv + (long)plane * NPIX;
    const float* kw = Wdw + ch * 9;
    float k0 = __ldg(kw+0), k1 = __ldg(kw+1), k2 = __ldg(kw+2);
    float k3 = __ldg(kw+3), k4 = __ldg(kw+4), k5 = __ldg(kw+5);
    float k6 = __ldg(kw+6), k7 = __ldg(kw+7), k8 = __ldg(kw+8);

    float row[3][6];
#pragma unroll
    for (int rr = 0; rr < 3; rr++) {
        int hh = h + rr - 1;
        if (hh >= 0 && hh < IMH) {
            const float* p = in + hh * IMW + w0;
            float4 cv = *(const float4*)p;
            row[rr][1] = cv.x; row[rr][2] = cv.y; row[rr][3] = cv.z; row[rr][4] = cv.w;
            row[rr][0] = (w0 > 0)       ? __ldg(p - 1) : 0.f;
            row[rr][5] = (w0 + 4 < IMW) ? __ldg(p + 4) : 0.f;
        } else {
#pragma unroll
            for (int j = 0; j < 6; j++) row[rr][j] = 0.f;
        }
    }

    float out[4];
#pragma unroll
    for (int j = 0; j < 4; j++) {
        out[j] = k0*row[0][j] + k1*row[0][j+1] + k2*row[0][j+2]
               + k3*row[1][j] + k4*row[1][j+1] + k5*row[1][j+2]
               + k6*row[2][j] + k7*row[2][j+1] + k8*row[2][j+2];
    }

    const int pix = h * IMW + w0;
    if (ch >= 2 * CHN) {
        int d = ch - 2 * CHN;
        const float* hw = g_hogw + (long)b * NORI * NPIX + pix;
#pragma unroll
        for (int o = 0; o < NORI; o++) {
            float wgt = __ldg(Whog + d * NORI + o);
            float4 hv = *(const float4*)(hw + (long)o * NPIX);
            out[0] += wgt * hv.x; out[1] += wgt * hv.y;
            out[2] += wgt * hv.z; out[3] += wgt * hv.w;
        }
    }
    *(float4*)(g_qkvdw + (long)plane * NPIX + pix) =
        make_float4(out[0], out[1], out[2], out[3]);

    if (ch < 2 * CHN) {
        float ss = out[0]*out[0] + out[1]*out[1] + out[2]*out[2] + out[3]*out[3];
#pragma unroll
        for (int o = 16; o > 0; o >>= 1) ss += __shfl_down_sync(0xffffffffu, ss, o);
        __shared__ float red[8];
        if (threadIdx.x == 0) red[threadIdx.y] = ss;
        __syncthreads();
        if (threadIdx.y == 0 && threadIdx.x == 0) {
            float s = 0.f;
#pragma unroll
            for (int i = 0; i < 8; i++) s += red[i];
            int which = ch / CHN;
            int r = which * (BATCH * CHN) + b * CHN + (ch - which * CHN);
            g_normp[r * 16 + blockIdx.y] = s;
        }
    }
}

// ============================================================
__global__ __launch_bounds__(256)
void norm_reduce_kernel()
{
    int r = blockIdx.x * 256 + threadIdx.x;
    if (r >= 2 * BATCH * CHN) return;
    float s = 0.f;
#pragma unroll
    for (int i = 0; i < 16; i++) s += g_normp[r * 16 + i];
    g_norms[r] = sqrtf(s);
}

// ============================================================
// reduce splits + normalize + softmax
// ============================================================
__global__ __launch_bounds__(64)
void softmax_kernel(const float* __restrict__ temp)
{
    const int blk = blockIdx.x;
    const int c  = blk % HDIM;
    const int bh = blk / HDIM;
    const int b = bh >> 2, hh = bh & 3;
    const int d = threadIdx.x;
    __shared__ float red[64];
    float val = -1e30f;
    if (d < HDIM) {
        const float* p = g_attnp + (long)bh * NSPLIT * HDIM * HDIM + c * HDIM + d;
        float s = 0.f;
#pragma unroll
        for (int sp = 0; sp < NSPLIT; sp++) s += p[(long)sp * HDIM * HDIM];
        float nq = g_norms[b * CHN + hh * HDIM + c];
        float nk = g_norms[BATCH * CHN + b * CHN + hh * HDIM + d];
        val = s / (fmaxf(nq, 1e-12f) * fmaxf(nk, 1e-12f)) * __ldg(temp + hh);
    }
    red[d] = val; __syncthreads();
    for (int o = 32; o > 0; o >>= 1) { if (d < o) red[d] = fmaxf(red[d], red[d + o]); __syncthreads(); }
    float mx = red[0]; __syncthreads();
    float e = (d < HDIM) ? expf(val - mx) : 0.f;
    red[d] = e; __syncthreads();
    for (int o = 32; o > 0; o >>= 1) { if (d < o) red[d] += red[d + o]; __syncthreads(); }
    if (d < HDIM)
        g_attn[(long)bh * HDIM * HDIM + c * HDIM + d] = e / red[0];
}

// ============================================================
// Fold W_proj with block-diagonal attn
// ============================================================
__global__ __launch_bounds__(256)
void wf_kernel(const float* __restrict__ Wproj)
{
    const int b = blockIdx.x, hh = blockIdx.y;
    __shared__ float at[HDIM][HDIM];
    const int t = threadIdx.x;
    for (int i = t; i < HDIM * HDIM; i += 256)
        at[i / HDIM][i % HDIM] = g_attn[(long)(b * NHEADS + hh) * HDIM * HDIM + i];
    __syncthreads();
    for (int i = t; i < CHN * HDIM; i += 256) {
        int e = i / HDIM, d = i - e * HDIM;
        const float* wp = Wproj + (long)e * CHN + hh * HDIM;
        float acc = 0.f;
#pragma unroll
        for (int c2 = 0; c2 < HDIM; c2++) acc += __ldg(wp + c2) * at[c2][d];
        g_wf[((long)b * CHN + e) * CHN + hh * HDIM + d] = acc;
    }
}

// ============================================================
extern "C" void kernel_launch(void* const* d_in, const int* in_sizes, int n_in,
                              void* d_out, int out_size)
{
    const float* x     = (const float*)d_in[0];
    const float* Wqkv  = (const float*)d_in[1];
    const float* Wdw   = (const float*)d_in[2];
    const float* Whog  = (const float*)d_in[3];
    const float* Wproj = (const float*)d_in[4];
    const float* temp  = (const float*)d_in[5];
    float* out = (float*)d_out;

    void *p_qkv, *p_qkvdw, *p_wf;
    cudaGetSymbolAddress(&p_qkv,   g_qkv);
    cudaGetSymbolAddress(&p_qkvdw, g_qkvdw);
    cudaGetSymbolAddress(&p_wf,    g_wf);

    const int gemm_smem = NB * (ASZ + BSZ) * 4;   // 88064
    const int attn_smem = 2 * NB * QSZ * 4;       // 55296
    cudaFuncSetAttribute(gemm_tf32_kernel,
                         cudaFuncAttributeMaxDynamicSharedMemorySize, gemm_smem);
    cudaFuncSetAttribute(attn_partial_kernel,
                         cudaFuncAttributeMaxDynamicSharedMemorySize, attn_smem);

    // 1) qkv = W_qkv @ x     (M=576, K=192, N=16384 per batch)
    gemm_tf32_kernel<<<dim3(NPIX / 256, CH3 / 64, BATCH), 256, gemm_smem>>>(
        Wqkv, 0L,
        x, (long)CHN * NPIX,
        (float*)p_qkv, (long)CH3 * NPIX,
        NPIX, CHN);

    // 2) Sobel + HOG bin weights
    sobel_hog_kernel<<<dim3(IMH, BATCH), 128>>>(x);

    // 3) depthwise 3x3 (+hog add on v, +norm partials on q/k)
    dwconv_hog_kernel<<<dim3(1, IMH / 8, BATCH * CH3), dim3(32, 8)>>>(Wdw, Whog);

    // 4) reduce norm partials
    norm_reduce_kernel<<<(2 * BATCH * CHN + 255) / 256, 256>>>();

    // 5) q.k^T partial dots (split-K) — tf32 MMA
    attn_partial_kernel<<<dim3(BATCH * NHEADS, NSPLIT), 192, attn_smem>>>();

    // 6) reduce + scale + softmax
    softmax_kernel<<<BATCH * NHEADS * HDIM, 64>>>(temp);

    // 7) fold W_proj with attn -> per-batch 192x192
    wf_kernel<<<dim3(BATCH, NHEADS), 256>>>(Wproj);

    // 8) out = Wf @ v         (M=192, K=192, N=16384 per batch)
    gemm_tf32_kernel<<<dim3(NPIX / 256, CHN / 64, BATCH), 256, gemm_smem>>>(
        (const float*)p_wf, (long)CHN * CHN,
        (const float*)p_qkvdw + (long)2 * CHN * NPIX, (long)CH3 * NPIX,
        out, (long)CHN * NPIX,
        NPIX, CHN);
}

// round 8
// speedup vs baseline: 1.9508x; 1.2396x over previous
#include <cuda_runtime.h>
#include <cuda_fp16.h>
#include <math.h>
#include <stdint.h>

#define BATCH 8
#define CHN 192
#define CH3 576
#define IMH 128
#define IMW 128
#define NPIX (IMH*IMW)         // 16384
#define NHEADS 4
#define HDIM 48
#define NORI 9
#define NSPLIT 32
#define SPLITLEN (NPIX/NSPLIT) // 512
#define PI_F 3.14159265358979323846f
#define NB 4                   // pipeline buffers (lookahead 2)

// ---- device scratch (no allocation allowed) ----
__device__ __half g_xh   [BATCH*CHN*NPIX];     // fp16 copy of x
__device__ __half g_wqkvh[CH3*CHN];            // fp16 W_qkv
__device__ __half g_qkv  [BATCH*CH3*NPIX];     // qkv (pre-dwconv), fp16
__device__ __half g_qkvdw[BATCH*CH3*NPIX];     // qkv (post-dwconv), fp16
__device__ __half g_wfh  [BATCH*CHN*CHN];      // folded W_proj*attn, fp16
__device__ float g_hogw [BATCH*NORI*NPIX];
__device__ float g_normp[2*BATCH*CHN*16];
__device__ float g_norms[2*BATCH*CHN];
__device__ float g_attnp[BATCH*NHEADS*NSPLIT*HDIM*HDIM];
__device__ float g_attn [BATCH*NHEADS*HDIM*HDIM];

__device__ __forceinline__ uint32_t smem_u32(const void* p) {
    return (uint32_t)__cvta_generic_to_shared(p);
}
__device__ __forceinline__ void cp_async16(uint32_t dst, const void* src) {
    asm volatile("cp.async.cg.shared.global [%0], [%1], 16;\n" :: "r"(dst), "l"(src));
}
__device__ __forceinline__ void cp_commit() {
    asm volatile("cp.async.commit_group;\n");
}
__device__ __forceinline__ void cp_wait2() {
    asm volatile("cp.async.wait_group 2;\n");
}
__device__ __forceinline__ float fast_sqrtf(float x) {
    float r; asm("sqrt.approx.f32 %0, %1;" : "=f"(r) : "f"(x)); return r;
}
__device__ __forceinline__ float fast_atan2f(float y, float x) {
    float ax = fabsf(x), ay = fabsf(y);
    float mx = fmaxf(ax, ay), mn = fminf(ax, ay);
    float a = __fdividef(mn, mx);
    float s = a * a;
    float r = -0.0117212f;
    r = fmaf(r, s,  0.05265332f);
    r = fmaf(r, s, -0.11643287f);
    r = fmaf(r, s,  0.19354346f);
    r = fmaf(r, s, -0.33262347f);
    r = fmaf(r, s,  0.99997726f);
    r = r * a;
    if (ay > ax) r = 1.57079632679f - r;
    if (x < 0.f) r = PI_F - r;
    return y < 0.f ? -r : r;
}

#define LDSM_X4(r0, r1, r2, r3, addr) \
    asm volatile("ldmatrix.sync.aligned.m8n8.x4.shared.b16 {%0,%1,%2,%3}, [%4];" \
                 : "=r"(r0), "=r"(r1), "=r"(r2), "=r"(r3) : "r"(addr))
#define LDSM_X4_T(r0, r1, r2, r3, addr) \
    asm volatile("ldmatrix.sync.aligned.m8n8.x4.trans.shared.b16 {%0,%1,%2,%3}, [%4];" \
                 : "=r"(r0), "=r"(r1), "=r"(r2), "=r"(r3) : "r"(addr))
#define LDSM_X2(r0, r1, addr) \
    asm volatile("ldmatrix.sync.aligned.m8n8.x2.shared.b16 {%0,%1}, [%2];" \
                 : "=r"(r0), "=r"(r1) : "r"(addr))

#define MMA_F16(d, a0, a1, a2, a3, b0, b1) \
    asm volatile( \
        "mma.sync.aligned.m16n8k16.row.col.f32.f16.f16.f32 " \
        "{%0,%1,%2,%3}, {%4,%5,%6,%7}, {%8,%9}, {%0,%1,%2,%3};\n" \
        : "+f"((d)[0]), "+f"((d)[1]), "+f"((d)[2]), "+f"((d)[3]) \
        : "r"(a0), "r"(a1), "r"(a2), "r"(a3), "r"(b0), "r"(b1))

// ============================================================
// float -> half conversion (4 elems/thread)
// ============================================================
__global__ __launch_bounds__(256)
void f2h_kernel(const float* __restrict__ src, __half* __restrict__ dst, int n)
{
    int i = (blockIdx.x * 256 + threadIdx.x) * 4;
    if (i < n) {
        float4 v = *(const float4*)(src + i);
        *(__half2*)(dst + i)     = __floats2half2_rn(v.x, v.y);
        *(__half2*)(dst + i + 2) = __floats2half2_rn(v.z, v.w);
    }
}

// ============================================================
// fp16 GEMM: C[z](MxN) = A[z](MxK fp16) * B[z](KxN fp16).
// BM=64 BN=256 BK=32, 256 thr (8 warps 2x4), warp tile 32x64.
// m16n8k16 MMA via ldmatrix, 4-buffer cp.async, one barrier/iter.
// As [m][k] stride 40 halves, Bs [k][n] stride 264 (both conflict-free
// for ldmatrix row patterns: 80B and 528B strides -> distinct mod-128).
// dyn smem = NB*(64*40 + 32*264)*2 = 88064 B. M%64, N%256, K%32 == 0.
// out_half: 1 -> C fp16, 0 -> C fp32.
// ============================================================
#define HASZ (64*40)
#define HBSZ (32*264)
__global__ __launch_bounds__(256, 2)
void gemm_h16_kernel(const __half* __restrict__ A, long sA,
                     const __half* __restrict__ B, long sB,
                     void* __restrict__ Cm, long sC,
                     int N, int K, int out_half)
{
    extern __shared__ __half hsmem[];
    __half* As = hsmem;              // NB stages 64x40
    __half* Bs = hsmem + NB * HASZ;  // NB stages 32x264

    const int t = threadIdx.x;
    const int lane = t & 31;
    const int warp = t >> 5;
    const int wm = warp >> 2;        // 0..1
    const int wn = warp & 3;         // 0..3
    const int m0 = blockIdx.y * 64;
    const int n0 = blockIdx.x * 256;
    const __half* Ab = A + (long)blockIdx.z * sA;
    const __half* Bb = B + (long)blockIdx.z * sB;

    const int kc = lane & 3;
    const int lq = lane >> 2;
    const int l15 = lane & 15;
    const int lh8 = (lane >> 4) * 8;

    const int niter = K / 32;

    float acc[2][8][4];
#pragma unroll
    for (int i = 0; i < 2; i++)
#pragma unroll
        for (int j = 0; j < 8; j++)
#pragma unroll
            for (int r = 0; r < 4; r++) acc[i][j][r] = 0.f;

    auto issue_stage = [&](int it) {
        const int stg = it & (NB - 1);
        const int k0 = it * 32;
        // A: 64 rows x 4 chunks of 8 halves
        cp_async16(smem_u32(&As[stg * HASZ + (t >> 2) * 40 + (t & 3) * 8]),
                   Ab + (long)(m0 + (t >> 2)) * K + k0 + (t & 3) * 8);
        // B: 32 rows x 32 chunks
#pragma unroll
        for (int j = 0; j < 4; j++) {
            int cch = (t & 7) + 8 * j;
            cp_async16(smem_u32(&Bs[stg * HBSZ + (t >> 3) * 264 + cch * 8]),
                       Bb + (long)(k0 + (t >> 3)) * N + n0 + cch * 8);
        }
    };

#pragma unroll
    for (int s = 0; s < 2; s++) {
        if (s < niter) issue_stage(s);
        cp_commit();
    }

    for (int it = 0; it < niter; it++) {
        if (it + 2 < niter) issue_stage(it + 2);
        cp_commit();
        cp_wait2();
        __syncthreads();

        const __half* Ast = As + (it & (NB - 1)) * HASZ;
        const __half* Bst = Bs + (it & (NB - 1)) * HBSZ;

#pragma unroll
        for (int ks = 0; ks < 2; ks++) {
            const int kb = ks * 16;
            uint32_t af[2][4], bf[8][2];
#pragma unroll
            for (int mt = 0; mt < 2; mt++) {
                uint32_t ad = smem_u32(Ast + (wm * 32 + mt * 16 + l15) * 40 + kb + lh8);
                LDSM_X4(af[mt][0], af[mt][1], af[mt][2], af[mt][3], ad);
            }
#pragma unroll
            for (int np = 0; np < 4; np++) {
                // rows: k = kb + ((lane>>3)&1)*8 + (lane&7); col: n_off + (lane>>4)*8
                int krow = kb + ((lane >> 3) & 1) * 8 + (lane & 7);
                int ncol = wn * 64 + np * 16 + lh8;
                uint32_t bd = smem_u32(Bst + krow * 264 + ncol);
                LDSM_X4_T(bf[np*2][0], bf[np*2][1], bf[np*2+1][0], bf[np*2+1][1], bd);
            }
#pragma unroll
            for (int mt = 0; mt < 2; mt++)
#pragma unroll
                for (int nt = 0; nt < 8; nt++)
                    MMA_F16(acc[mt][nt], af[mt][0], af[mt][1], af[mt][2], af[mt][3],
                            bf[nt][0], bf[nt][1]);
        }
    }

    if (out_half) {
        __half* Cb = (__half*)Cm + (long)blockIdx.z * sC;
#pragma unroll
        for (int mt = 0; mt < 2; mt++) {
            int r = m0 + wm * 32 + mt * 16 + lq;
#pragma unroll
            for (int nt = 0; nt < 8; nt++) {
                int c = n0 + wn * 64 + nt * 8 + kc * 2;
                *(__half2*)(Cb + (long)r * N + c) =
                    __floats2half2_rn(acc[mt][nt][0], acc[mt][nt][1]);
                *(__half2*)(Cb + (long)(r + 8) * N + c) =
                    __floats2half2_rn(acc[mt][nt][2], acc[mt][nt][3]);
            }
        }
    } else {
        float* Cb = (float*)Cm + (long)blockIdx.z * sC;
#pragma unroll
        for (int mt = 0; mt < 2; mt++) {
            int r = m0 + wm * 32 + mt * 16 + lq;
#pragma unroll
            for (int nt = 0; nt < 8; nt++) {
                int c = n0 + wn * 64 + nt * 8 + kc * 2;
                *(float2*)(Cb + (long)r * N + c) =
                    make_float2(acc[mt][nt][0], acc[mt][nt][1]);
                *(float2*)(Cb + (long)(r + 8) * N + c) =
                    make_float2(acc[mt][nt][2], acc[mt][nt][3]);
            }
        }
    }
}

// ============================================================
// attn partial via fp16 MMA: S[bh,split][48][48] = Q_tile @ K_tile^T.
// 192 thr (6 warps: wm 0..2 -> 16 rows, wn 0..1 -> 24 cols).
// K smem [n][k]-major == col-major B fragment -> non-trans ldmatrix x2.
// Qs/Ks [chan][px] stride 40 halves. dyn smem = 2*NB*48*40*2 = 30720 B.
// ============================================================
#define HQSZ (48*40)
__global__ __launch_bounds__(192, 4)
void attn_partial_kernel()
{
    extern __shared__ __half hsmem[];
    __half* Qs = hsmem;              // NB stages 48x40
    __half* Ks = hsmem + NB * HQSZ;

    const int bh = blockIdx.x;
    const int split = blockIdx.y;
    const int b = bh >> 2, hh = bh & 3;
    const __half* Qg = g_qkvdw + ((long)b * CH3 + hh * HDIM) * NPIX;
    const __half* Kg = g_qkvdw + ((long)b * CH3 + CHN + hh * HDIM) * NPIX;
    const int nbase = split * SPLITLEN;

    const int t = threadIdx.x;
    const int lane = t & 31;
    const int warp = t >> 5;
    const int wm = warp % 3;
    const int wn = warp / 3;
    const int kc = lane & 3;
    const int lq = lane >> 2;
    const int l15 = lane & 15;

    float acc[3][4];
#pragma unroll
    for (int i = 0; i < 3; i++)
#pragma unroll
        for (int r = 0; r < 4; r++) acc[i][r] = 0.f;

    const int niter = SPLITLEN / 32;   // 16 chunks of 32 px

    auto issue_stage = [&](int it) {
        const int stg = it & (NB - 1);
        const int base = nbase + it * 32;
        int r = t >> 2, c4 = t & 3;      // 48 rows x 4 chunks = 192
        cp_async16(smem_u32(&Qs[stg * HQSZ + r * 40 + c4 * 8]),
                   Qg + (long)r * NPIX + base + c4 * 8);
        cp_async16(smem_u32(&Ks[stg * HQSZ + r * 40 + c4 * 8]),
                   Kg + (long)r * NPIX + base + c4 * 8);
    };

#pragma unroll
    for (int s = 0; s < 2; s++) {
        if (s < niter) issue_stage(s);
        cp_commit();
    }

    for (int it = 0; it < niter; it++) {
        if (it + 2 < niter) issue_stage(it + 2);
        cp_commit();
        cp_wait2();
        __syncthreads();

        const __half* Qst = Qs + (it & (NB - 1)) * HQSZ;
        const __half* Kst = Ks + (it & (NB - 1)) * HQSZ;

#pragma unroll
        for (int ks = 0; ks < 2; ks++) {
            const int kb = ks * 16;
            uint32_t af[4], bf[3][2];
            {
                uint32_t ad = smem_u32(Qst + (wm * 16 + l15) * 40 + kb + (lane >> 4) * 8);
                LDSM_X4(af[0], af[1], af[2], af[3], ad);
            }
#pragma unroll
            for (int nt = 0; nt < 3; nt++) {
                // lanes 0-7: rows n, k-chunk 0; lanes 8-15: rows n, k-chunk +8
                int nrow = wn * 24 + nt * 8 + (l15 & 7);
                int kcol = kb + ((l15 >> 3) & 1) * 8;
                uint32_t bd = smem_u32(Kst + nrow * 40 + kcol);
                LDSM_X2(bf[nt][0], bf[nt][1], bd);
            }
#pragma unroll
            for (int nt = 0; nt < 3; nt++)
                MMA_F16(acc[nt], af[0], af[1], af[2], af[3], bf[nt][0], bf[nt][1]);
        }
    }

    float* dst = g_attnp + ((long)bh * NSPLIT + split) * HDIM * HDIM;
    int row = wm * 16 + lq;
#pragma unroll
    for (int nt = 0; nt < 3; nt++) {
        int col = wn * 24 + nt * 8 + kc * 2;
        *(float2*)(dst + row * HDIM + col) = make_float2(acc[nt][0], acc[nt][1]);
        *(float2*)(dst + (row + 8) * HDIM + col) = make_float2(acc[nt][2], acc[nt][3]);
    }
}

// ============================================================
// Sobel (replicate pad, /8 kernels) -> channel-mean mag/ang -> HOG weights
// ============================================================
__global__ __launch_bounds__(128)
void sobel_hog_kernel(const float* __restrict__ x)
{
    const int w = threadIdx.x;
    const int h = blockIdx.x;
    const int b = blockIdx.y;
    const int hm = h > 0 ? h - 1 : 0;
    const int hp = h < IMH - 1 ? h + 1 : IMH - 1;
    const int wm = w > 0 ? w - 1 : 0;
    const int wp = w < IMW - 1 ? w + 1 : IMW - 1;
    const float* xb = x + (long)b * CHN * NPIX;

    float msum = 0.f, asum = 0.f;
    for (int c = 0; c < CHN; c++) {
        const float* p = xb + (long)c * NPIX;
        float a00 = __ldg(p + hm*IMW + wm), a01 = __ldg(p + hm*IMW + w), a02 = __ldg(p + hm*IMW + wp);
        float a10 = __ldg(p + h *IMW + wm),                              a12 = __ldg(p + h *IMW + wp);
        float a20 = __ldg(p + hp*IMW + wm), a21 = __ldg(p + hp*IMW + w), a22 = __ldg(p + hp*IMW + wp);
        float dx = (a02 - a00 + 2.f*(a12 - a10) + a22 - a20) * 0.125f;
        float dy = (a20 - a00 + 2.f*(a21 - a01) + a22 - a02) * 0.125f;
        msum += fast_sqrtf(dx*dx + dy*dy + 1e-6f);
        asum += fast_atan2f(dy, dx + 1e-6f);
    }
    float mag = msum * (1.f / CHN);
    float ang = asum * (1.f / CHN);
    ang = ang - PI_F * floorf(ang / PI_F);
    const float binw = PI_F / NORI;
    const int pix = h * IMW + w;
#pragma unroll
    for (int o = 0; o < NORI; o++) {
        float cen = ((float)o + 0.5f) * binw;
        float wgt = 1.f - fabsf(ang - cen) / binw;
        wgt = wgt > 0.f ? wgt : 0.f;
        g_hogw[((long)b * NORI + o) * NPIX + pix] = wgt * mag;
    }
}

// ============================================================
// Depthwise 3x3 SAME (zero pad), 4 px/thread, fp16 in/out,
// fused HOG add on v channels, fused norm partials on q/k.
// ============================================================
__global__ __launch_bounds__(256)
void dwconv_hog_kernel(const float* __restrict__ Wdw, const float* __restrict__ Whog)
{
    const int plane = blockIdx.z;
    const int b  = plane / CH3;
    const int ch = plane - b * CH3;
    const int w0 = threadIdx.x * 4;
    const int h  = blockIdx.y * 8 + threadIdx.y;
    const __half* in = g_qkv + (long)plane * NPIX;
    const float* kw = Wdw + ch * 9;
    float k0 = __ldg(kw+0), k1 = __ldg(kw+1), k2 = __ldg(kw+2);
    float k3 = __ldg(kw+3), k4 = __ldg(kw+4), k5 = __ldg(kw+5);
    float k6 = __ldg(kw+6), k7 = __ldg(kw+7), k8 = __ldg(kw+8);

    float row[3][6];
#pragma unroll
    for (int rr = 0; rr < 3; rr++) {
        int hh = h + rr - 1;
        if (hh >= 0 && hh < IMH) {
            const __half* p = in + hh * IMW + w0;
            __half2 c0 = *(const __half2*)p;
            __half2 c1 = *(const __half2*)(p + 2);
            float2 f0 = __half22float2(c0), f1 = __half22float2(c1);
            row[rr][1] = f0.x; row[rr][2] = f0.y; row[rr][3] = f1.x; row[rr][4] = f1.y;
            row[rr][0] = (w0 > 0)       ? __half2float(p[-1]) : 0.f;
            row[rr][5] = (w0 + 4 < IMW) ? __half2float(p[4])  : 0.f;
        } else {
#pragma unroll
            for (int j = 0; j < 6; j++) row[rr][j] = 0.f;
        }
    }

    float out[4];
#pragma unroll
    for (int j = 0; j < 4; j++) {
        out[j] = k0*row[0][j] + k1*row[0][j+1] + k2*row[0][j+2]
               + k3*row[1][j] + k4*row[1][j+1] + k5*row[1][j+2]
               + k6*row[2][j] + k7*row[2][j+1] + k8*row[2][j+2];
    }

    const int pix = h * IMW + w0;
    if (ch >= 2 * CHN) {
        int d = ch - 2 * CHN;
        const float* hw = g_hogw + (long)b * NORI * NPIX + pix;
#pragma unroll
        for (int o = 0; o < NORI; o++) {
            float wgt = __ldg(Whog + d * NORI + o);
            float4 hv = *(const float4*)(hw + (long)o * NPIX);
            out[0] += wgt * hv.x; out[1] += wgt * hv.y;
            out[2] += wgt * hv.z; out[3] += wgt * hv.w;
        }
    }
    __half2 o01 = __floats2half2_rn(out[0], out[1]);
    __half2 o23 = __floats2half2_rn(out[2], out[3]);
    __half* dst = g_qkvdw + (long)plane * NPIX + pix;
    *(__half2*)dst = o01;
    *(__half2*)(dst + 2) = o23;

    if (ch < 2 * CHN) {
        // norms from the ROUNDED values (what downstream MMA consumes)
        float2 r01 = __half22float2(o01), r23 = __half22float2(o23);
        float ss = r01.x*r01.x + r01.y*r01.y + r23.x*r23.x + r23.y*r23.y;
#pragma unroll
        for (int o = 16; o > 0; o >>= 1) ss += __shfl_down_sync(0xffffffffu, ss, o);
        __shared__ float red[8];
        if (threadIdx.x == 0) red[threadIdx.y] = ss;
        __syncthreads();
        if (threadIdx.y == 0 && threadIdx.x == 0) {
            float s = 0.f;
#pragma unroll
            for (int i = 0; i < 8; i++) s += red[i];
            int which = ch / CHN;
            int r = which * (BATCH * CHN) + b * CHN + (ch - which * CHN);
            g_normp[r * 16 + blockIdx.y] = s;
        }
    }
}

// ============================================================
__global__ __launch_bounds__(256)
void norm_reduce_kernel()
{
    int r = blockIdx.x * 256 + threadIdx.x;
    if (r >= 2 * BATCH * CHN) return;
    float s = 0.f;
#pragma unroll
    for (int i = 0; i < 16; i++) s += g_normp[r * 16 + i];
    g_norms[r] = sqrtf(s);
}

// ============================================================
// reduce splits + normalize + softmax
// ============================================================
__global__ __launch_bounds__(64)
void softmax_kernel(const float* __restrict__ temp)
{
    const int blk = blockIdx.x;
    const int c  = blk % HDIM;
    const int bh = blk / HDIM;
    const int b = bh >> 2, hh = bh & 3;
    const int d = threadIdx.x;
    __shared__ float red[64];
    float val = -1e30f;
    if (d < HDIM) {
        const float* p = g_attnp + (long)bh * NSPLIT * HDIM * HDIM + c * HDIM + d;
        float s = 0.f;
#pragma unroll
        for (int sp = 0; sp < NSPLIT; sp++) s += p[(long)sp * HDIM * HDIM];
        float nq = g_norms[b * CHN + hh * HDIM + c];
        float nk = g_norms[BATCH * CHN + b * CHN + hh * HDIM + d];
        val = s / (fmaxf(nq, 1e-12f) * fmaxf(nk, 1e-12f)) * __ldg(temp + hh);
    }
    red[d] = val; __syncthreads();
    for (int o = 32; o > 0; o >>= 1) { if (d < o) red[d] = fmaxf(red[d], red[d + o]); __syncthreads(); }
    float mx = red[0]; __syncthreads();
    float e = (d < HDIM) ? expf(val - mx) : 0.f;
    red[d] = e; __syncthreads();
    for (int o = 32; o > 0; o >>= 1) { if (d < o) red[d] += red[d + o]; __syncthreads(); }
    if (d < HDIM)
        g_attn[(long)bh * HDIM * HDIM + c * HDIM + d] = e / red[0];
}

// ============================================================
// Fold W_proj with block-diagonal attn -> fp16 Wf
// ============================================================
__global__ __launch_bounds__(256)
void wf_kernel(const float* __restrict__ Wproj)
{
    const int b = blockIdx.x, hh = blockIdx.y;
    __shared__ float at[HDIM][HDIM];
    const int t = threadIdx.x;
    for (int i = t; i < HDIM * HDIM; i += 256)
        at[i / HDIM][i % HDIM] = g_attn[(long)(b * NHEADS + hh) * HDIM * HDIM + i];
    __syncthreads();
    for (int i = t; i < CHN * HDIM; i += 256) {
        int e = i / HDIM, d = i - e * HDIM;
        const float* wp = Wproj + (long)e * CHN + hh * HDIM;
        float acc = 0.f;
#pragma unroll
        for (int c2 = 0; c2 < HDIM; c2++) acc += __ldg(wp + c2) * at[c2][d];
        g_wfh[((long)b * CHN + e) * CHN + hh * HDIM + d] = __float2half_rn(acc);
    }
}

// ============================================================
extern "C" void kernel_launch(void* const* d_in, const int* in_sizes, int n_in,
                              void* d_out, int out_size)
{
    const float* x     = (const float*)d_in[0];
    const float* Wqkv  = (const float*)d_in[1];
    const float* Wdw   = (const float*)d_in[2];
    const float* Whog  = (const float*)d_in[3];
    const float* Wproj = (const float*)d_in[4];
    const float* temp  = (const float*)d_in[5];
    float* out = (float*)d_out;

    void *p_xh, *p_wqkvh, *p_qkv, *p_qkvdw, *p_wfh;
    cudaGetSymbolAddress(&p_xh,    g_xh);
    cudaGetSymbolAddress(&p_wqkvh, g_wqkvh);
    cudaGetSymbolAddress(&p_qkv,   g_qkv);
    cudaGetSymbolAddress(&p_qkvdw, g_qkvdw);
    cudaGetSymbolAddress(&p_wfh,   g_wfh);

    const int gemm_smem = NB * (HASZ + HBSZ) * 2;   // 88064
    const int attn_smem = 2 * NB * HQSZ * 2;        // 30720
    cudaFuncSetAttribute(gemm_h16_kernel,
                         cudaFuncAttributeMaxDynamicSharedMemorySize, gemm_smem);
    cudaFuncSetAttribute(attn_partial_kernel,
                         cudaFuncAttributeMaxDynamicSharedMemorySize, attn_smem);

    // 0) fp16 conversions
    f2h_kernel<<<(BATCH*CHN*NPIX/4 + 255)/256, 256>>>(x, (__half*)p_xh, BATCH*CHN*NPIX);
    f2h_kernel<<<(CH3*CHN/4 + 255)/256, 256>>>(Wqkv, (__half*)p_wqkvh, CH3*CHN);

    // 1) qkv = W_qkv @ x  (fp16 MMA, fp16 out)
    gemm_h16_kernel<<<dim3(NPIX / 256, CH3 / 64, BATCH), 256, gemm_smem>>>(
        (const __half*)p_wqkvh, 0L,
        (const __half*)p_xh, (long)CHN * NPIX,
        p_qkv, (long)CH3 * NPIX,
        NPIX, CHN, 1);

    // 2) Sobel + HOG bin weights (fp32 x)
    sobel_hog_kernel<<<dim3(IMH, BATCH), 128>>>(x);

    // 3) depthwise 3x3 (+hog on v, +norm partials on q/k), fp16 IO
    dwconv_hog_kernel<<<dim3(1, IMH / 8, BATCH * CH3), dim3(32, 8)>>>(Wdw, Whog);

    // 4) reduce norm partials
    norm_reduce_kernel<<<(2 * BATCH * CHN + 255) / 256, 256>>>();

    // 5) q.k^T partial dots (split-K), fp16 MMA
    attn_partial_kernel<<<dim3(BATCH * NHEADS, NSPLIT), 192, attn_smem>>>();

    // 6) reduce + scale + softmax
    softmax_kernel<<<BATCH * NHEADS * HDIM, 64>>>(temp);

    // 7) fold W_proj with attn -> per-batch 192x192 fp16
    wf_kernel<<<dim3(BATCH, NHEADS), 256>>>(Wproj);

    // 8) out = Wf @ v  (fp16 MMA, fp32 out)
    gemm_h16_kernel<<<dim3(NPIX / 256, CHN / 64, BATCH), 256, gemm_smem>>>(
        (const __half*)p_wfh, (long)CHN * CHN,
        (const __half*)p_qkvdw + (long)2 * CHN * NPIX, (long)CH3 * NPIX,
        d_out, (long)CHN * NPIX,
        NPIX, CHN, 0);
}